// round 6
// baseline (speedup 1.0000x reference)
#include <cuda_runtime.h>
#include <math.h>
#include <stdint.h>

#define BATCH 4
#define S_LEN 2048
#define D_DIM 1024
#define NH    16
#define DH    64
#define M_TOT (BATCH*S_LEN)

__device__ float  g_Q[BATCH*NH*S_LEN*DH];
__device__ float  g_K[BATCH*NH*S_LEN*DH];
__device__ float  g_V[BATCH*NH*S_LEN*DH];
__device__ float  g_H[M_TOT*D_DIM];          // attention out, tf32-rounded + pair-permuted
__device__ float  g_Xp[M_TOT*D_DIM];         // X converted+permuted
__device__ float  g_Wp[4*D_DIM*D_DIM];       // Wq,Wk,Wv,Wo converted+permuted
__device__ float2 g_tab[S_LEN*(D_DIM/2)];

__device__ __forceinline__ unsigned f2tf(float x){
    unsigned u; asm("cvt.rna.tf32.f32 %0, %1;" : "=r"(u) : "f"(x)); return u;
}
__device__ __forceinline__ float tfr(float x){ return __uint_as_float(f2tf(x)); }
__device__ __forceinline__ uint32_t smem_u32(const void* p){
    uint32_t a;
    asm("{ .reg .u64 t; cvta.to.shared.u64 t, %1; cvt.u32.u64 %0, t; }" : "=r"(a) : "l"(p));
    return a;
}
__device__ __forceinline__ void cp16(uint32_t dst, const void* src){
    asm volatile("cp.async.cg.shared.global [%0], [%1], 16;" :: "r"(dst), "l"(src) : "memory");
}
#define CP_COMMIT() asm volatile("cp.async.commit_group;" ::: "memory")
#define CP_WAIT(n)  asm volatile("cp.async.wait_group %0;" :: "n"(n) : "memory")

__device__ __forceinline__ void mma8(float* c, const unsigned* a, const unsigned* b){
    asm volatile("mma.sync.aligned.m16n8k8.row.col.f32.tf32.tf32.f32 "
        "{%0,%1,%2,%3}, {%4,%5,%6,%7}, {%8,%9}, {%0,%1,%2,%3};"
        : "+f"(c[0]), "+f"(c[1]), "+f"(c[2]), "+f"(c[3])
        : "r"(a[0]), "r"(a[1]), "r"(a[2]), "r"(a[3]), "r"(b[0]), "r"(b[1]));
}

__global__ void rope_table_kernel(){
    int idx = blockIdx.x*blockDim.x + threadIdx.x;
    if (idx >= S_LEN*512) return;
    int s = idx >> 9, p = idx & 511;
    double inv = exp(-((double)(2*p)/(double)D_DIM)*log(10000.0));
    float sn, cs; sincosf((float)s*(float)inv, &sn, &cs);
    g_tab[idx] = make_float2(cs, sn);
}

// tf32-round + permute each 8-group to (k0,k4,k1,k5,k2,k6,k3,k7)
__global__ void conv_perm(const float* __restrict__ src, float* __restrict__ dst, int ngroups){
    int g = blockIdx.x*blockDim.x + threadIdx.x;
    if (g >= ngroups) return;
    const float4* s = (const float4*)src + (size_t)g*2;
    float4 v0 = s[0], v1 = s[1];
    uint4 o0 = make_uint4(f2tf(v0.x), f2tf(v1.x), f2tf(v0.y), f2tf(v1.y));
    uint4 o1 = make_uint4(f2tf(v0.z), f2tf(v1.z), f2tf(v0.w), f2tf(v1.w));
    uint4* d = (uint4*)dst + (size_t)g*2;
    d[0] = o0; d[1] = o1;
}

// ============ GEMM v4: out = A[M,1024] @ W[N,1024]^T + bias ============
// A, W pre-converted + pair-permuted. 4 warps, warp 64x64, CTA 128x128.
// smem: 4 stages x (A:128rows + B:128rows) x 12 uint2 stride (8 pairs + pad).
// MODE 0: plain fp32 [M,N]; MODE 1: rounded scatter [B,H,S,dh]; MODE 2: RoPE+round+scatter
template<int MODE>
__global__ __launch_bounds__(128,2) void gemm_v4(
    const float* __restrict__ Ap, const float* __restrict__ Wp,
    const float* __restrict__ bias, float* __restrict__ out)
{
    extern __shared__ uint32_t sm4[];
    uint32_t sbase = smem_u32(sm4);
    int tid = threadIdx.x, lane = tid & 31, w = tid >> 5;
    int rr = lane >> 2, cb = lane & 3;
    int wm = (w >> 1)*64, wn = (w & 1)*64;
    int m0 = blockIdx.y*128, n0 = blockIdx.x*128;

    float acc[4][8][4];
    #pragma unroll
    for (int i=0;i<4;i++)
        #pragma unroll
        for (int j=0;j<8;j++)
            #pragma unroll
            for (int e=0;e<4;e++) acc[i][j][e] = 0.f;

    const float* Arow = Ap + (size_t)(m0 + tid)*D_DIM;
    const float* Wrow = Wp + (size_t)(n0 + tid)*D_DIM;
    uint32_t dA = sbase + tid*96;            // + stage*24576 + i*16
    uint32_t dB = sbase + 12288 + tid*96;

    #pragma unroll
    for (int c = 0; c < 2; c++){
        #pragma unroll
        for (int i=0;i<4;i++){
            cp16(dA + c*24576 + i*16, Arow + c*16 + i*4);
            cp16(dB + c*24576 + i*16, Wrow + c*16 + i*4);
        }
        CP_COMMIT();
    }

    for (int it = 0; it < 64; it++){
        if (it + 2 < 64){
            int c = it + 2, s2 = c & 3;
            #pragma unroll
            for (int i=0;i<4;i++){
                cp16(dA + s2*24576 + i*16, Arow + c*16 + i*4);
                cp16(dB + s2*24576 + i*16, Wrow + c*16 + i*4);
            }
            CP_COMMIT();
            CP_WAIT(2);
        } else {
            CP_WAIT(0);
        }
        __syncthreads();
        const uint2* Sa = (const uint2*)sm4 + (it & 3)*3072;
        const uint2* Sb = Sa + 1536;
        #pragma unroll
        for (int ks = 0; ks < 2; ks++){
            int p = 4*ks + cb;
            unsigned a[4][4], b[8][2];
            #pragma unroll
            for (int fm = 0; fm < 4; fm++){
                uint2 l0 = Sa[(wm + rr + 16*fm)*12 + p];
                uint2 l1 = Sa[(wm + rr + 16*fm + 8)*12 + p];
                a[fm][0]=l0.x; a[fm][1]=l1.x; a[fm][2]=l0.y; a[fm][3]=l1.y;
            }
            #pragma unroll
            for (int fn = 0; fn < 8; fn++){
                uint2 l = Sb[(wn + rr + 8*fn)*12 + p];
                b[fn][0]=l.x; b[fn][1]=l.y;
            }
            #pragma unroll
            for (int fm = 0; fm < 4; fm++)
                #pragma unroll
                for (int fn = 0; fn < 8; fn++)
                    mma8(acc[fm][fn], a[fm], b[fn]);
        }
    }

    #pragma unroll
    for (int fn = 0; fn < 8; fn++){
        int colg = n0 + wn + fn*8 + cb*2;
        float b0v = bias[colg], b1v = bias[colg+1];
        #pragma unroll
        for (int fm = 0; fm < 4; fm++){
            #pragma unroll
            for (int half = 0; half < 2; half++){
                int m = m0 + wm + fm*16 + rr + half*8;
                float v0 = acc[fm][fn][half*2+0] + b0v;
                float v1 = acc[fm][fn][half*2+1] + b1v;
                int srow = m & (S_LEN-1);
                if (MODE == 2){
                    float2 cs = g_tab[srow*512 + (colg >> 1)];
                    float e = v0*cs.x - v1*cs.y;
                    float d = v0*cs.y + v1*cs.x;
                    v0 = e; v1 = d;
                }
                if (MODE == 0){
                    *(float2*)(out + (size_t)m*D_DIM + colg) = make_float2(v0, v1);
                } else {
                    int bb = m >> 11, hh = colg >> 6, dd = colg & 63;
                    *(float2*)(out + ((size_t)(bb*NH+hh)*S_LEN + srow)*DH + dd) =
                        make_float2(tfr(v0), tfr(v1));
                }
            }
        }
    }
}

// ============ Flash attention (R5 structure; Q/K/V pre-rounded, H written rounded+permuted) ============
__global__ __launch_bounds__(256,1) void attn_v3(
    const float* __restrict__ Q, const float* __restrict__ K,
    const float* __restrict__ V, float* __restrict__ O)
{
    extern __shared__ unsigned sm[];
    int tid = threadIdx.x, lane = tid & 31, w = tid >> 5;
    int rr = lane >> 2, cb = lane & 3;
    int qb = blockIdx.x, hd = blockIdx.y, b = blockIdx.z;

    const float* Qp = Q + ((size_t)(b*NH + hd)*S_LEN + qb*256 + w*32)*DH;
    const float* Kp = K + (size_t)(b*NH + hd)*S_LEN*DH;
    const float* Vp = V + (size_t)(b*NH + hd)*S_LEN*DH;
    unsigned* Pw = sm + 18432 + (w*32)*72;

    unsigned q[2][8][4];
    #pragma unroll
    for (int fm = 0; fm < 2; fm++){
        int r0 = fm*16 + rr;
        #pragma unroll
        for (int ks = 0; ks < 8; ks++){
            int c = ks*8 + cb;
            q[fm][ks][0] = __float_as_uint(0.125f * Qp[(size_t)r0*DH + c]);
            q[fm][ks][1] = __float_as_uint(0.125f * Qp[(size_t)(r0+8)*DH + c]);
            q[fm][ks][2] = __float_as_uint(0.125f * Qp[(size_t)r0*DH + c+4]);
            q[fm][ks][3] = __float_as_uint(0.125f * Qp[(size_t)(r0+8)*DH + c+4]);
        }
    }

    float m_[2][2], l_[2][2], o[2][8][4];
    #pragma unroll
    for (int fm=0;fm<2;fm++)
        #pragma unroll
        for (int hh=0;hh<2;hh++){ m_[fm][hh] = -1e30f; l_[fm][hh] = 0.f; }
    #pragma unroll
    for (int fm=0;fm<2;fm++)
        #pragma unroll
        for (int fn=0;fn<8;fn++)
            #pragma unroll
            for (int e=0;e<4;e++) o[fm][fn][e] = 0.f;

    float4 kst[4], vst[4];
    #pragma unroll
    for (int l=0;l<4;l++){ int slot = tid + l*256; int kp = slot>>4, cq = slot&15;
        kst[l] = *(const float4*)(Kp + (size_t)kp*DH + cq*4);
        vst[l] = *(const float4*)(Vp + (size_t)kp*DH + cq*4); }
    #pragma unroll
    for (int l=0;l<4;l++){ int slot = tid + l*256; int kp = slot>>4, cq = slot&15;
        const float* kv = (const float*)&kst[l];
        const float* vv = (const float*)&vst[l];
        #pragma unroll
        for (int j=0;j<4;j++){
            sm[(cq*4+j)*72 + ((kp + 2*cq) & 63)] = __float_as_uint(kv[j]);
            sm[9216 + kp*72 + ((cq*4+j + 2*(kp>>2)) & 63)] = __float_as_uint(vv[j]); } }
    __syncthreads();

    for (int t = 0; t < 32; t++){
        int cur = t & 1;
        const unsigned* Kc = sm + cur*4608;
        const unsigned* Vc = sm + 9216 + cur*4608;
        if (t + 1 < 32){
            const float* Kn = Kp + (size_t)(t+1)*64*DH;
            const float* Vn = Vp + (size_t)(t+1)*64*DH;
            #pragma unroll
            for (int l=0;l<4;l++){ int slot = tid + l*256; int kp = slot>>4, cq = slot&15;
                kst[l] = *(const float4*)(Kn + (size_t)kp*DH + cq*4);
                vst[l] = *(const float4*)(Vn + (size_t)kp*DH + cq*4); }
        }

        float s[2][8][4];
        #pragma unroll
        for (int fm=0;fm<2;fm++)
            #pragma unroll
            for (int fn=0;fn<8;fn++)
                #pragma unroll
                for (int e=0;e<4;e++) s[fm][fn][e] = 0.f;

        #pragma unroll
        for (int ks = 0; ks < 8; ks++){
            int c1 = ks*8 + cb;
            #pragma unroll
            for (int fn = 0; fn < 8; fn++){
                int n = fn*8 + rr;
                unsigned bb[2];
                bb[0] = Kc[c1*72 + ((n + 4*ks) & 63)];
                bb[1] = Kc[(c1+4)*72 + ((n + 4*ks + 2) & 63)];
                mma8(s[0][fn], q[0][ks], bb);
                mma8(s[1][fn], q[1][ks], bb);
            }
        }

        #pragma unroll
        for (int fm = 0; fm < 2; fm++)
            #pragma unroll
            for (int hh = 0; hh < 2; hh++){
                float rm = -1e30f;
                #pragma unroll
                for (int fn = 0; fn < 8; fn++)
                    rm = fmaxf(rm, fmaxf(s[fm][fn][hh*2], s[fm][fn][hh*2+1]));
                rm = fmaxf(rm, __shfl_xor_sync(0xffffffffu, rm, 1));
                rm = fmaxf(rm, __shfl_xor_sync(0xffffffffu, rm, 2));
                float mn = fmaxf(m_[fm][hh], rm);
                float sum = 0.f;
                #pragma unroll
                for (int fn = 0; fn < 8; fn++){
                    s[fm][fn][hh*2]   = __expf(s[fm][fn][hh*2]   - mn);
                    s[fm][fn][hh*2+1] = __expf(s[fm][fn][hh*2+1] - mn);
                    sum += s[fm][fn][hh*2] + s[fm][fn][hh*2+1];
                }
                sum += __shfl_xor_sync(0xffffffffu, sum, 1);
                sum += __shfl_xor_sync(0xffffffffu, sum, 2);
                float alpha = __expf(m_[fm][hh] - mn);
                l_[fm][hh] = l_[fm][hh]*alpha + sum;
                m_[fm][hh] = mn;
                #pragma unroll
                for (int fn = 0; fn < 8; fn++){
                    o[fm][fn][hh*2]   *= alpha;
                    o[fm][fn][hh*2+1] *= alpha;
                }
            }

        #pragma unroll
        for (int fm = 0; fm < 2; fm++)
            #pragma unroll
            for (int hh = 0; hh < 2; hh++){
                int rl = fm*16 + rr + 8*hh;
                int ro = 4*(rl>>2);
                #pragma unroll
                for (int fn = 0; fn < 8; fn++){
                    int pc = fn*8 + cb*2;
                    *(uint2*)&Pw[rl*72 + ((pc + ro) & 63)] =
                        make_uint2(f2tf(s[fm][fn][hh*2]), f2tf(s[fm][fn][hh*2+1]));
                }
            }
        __syncwarp();

        #pragma unroll
        for (int ks = 0; ks < 8; ks++){
            int kc = ks*8 + cb;
            unsigned a[2][4];
            #pragma unroll
            for (int fm = 0; fm < 2; fm++){
                int r0 = fm*16 + rr, r1 = r0 + 8;
                a[fm][0] = Pw[r0*72 + ((kc + 4*(r0>>2)) & 63)];
                a[fm][1] = Pw[r1*72 + ((kc + 4*(r1>>2)) & 63)];
                a[fm][2] = Pw[r0*72 + ((kc + 4 + 4*(r0>>2)) & 63)];
                a[fm][3] = Pw[r1*72 + ((kc + 4 + 4*(r1>>2)) & 63)];
            }
            #pragma unroll
            for (int fn = 0; fn < 8; fn++){
                int n = fn*8 + rr;
                unsigned bb[2];
                bb[0] = Vc[kc*72 + ((n + 4*ks) & 63)];
                bb[1] = Vc[(kc+4)*72 + ((n + 4*ks + 2) & 63)];
                mma8(o[0][fn], a[0], bb);
                mma8(o[1][fn], a[1], bb);
            }
        }

        __syncthreads();
        if (t + 1 < 32){
            unsigned* Kw = sm + (cur^1)*4608;
            unsigned* Vw = sm + 9216 + (cur^1)*4608;
            #pragma unroll
            for (int l=0;l<4;l++){ int slot = tid + l*256; int kp = slot>>4, cq = slot&15;
                const float* kv = (const float*)&kst[l];
                const float* vv = (const float*)&vst[l];
                #pragma unroll
                for (int j=0;j<4;j++){
                    Kw[(cq*4+j)*72 + ((kp + 2*cq) & 63)] = __float_as_uint(kv[j]);
                    Vw[kp*72 + ((cq*4+j + 2*(kp>>2)) & 63)] = __float_as_uint(vv[j]); } }
            __syncthreads();
        }
    }

    // Writeback: tf32-rounded + pair-permuted within each 8-group (for gemm_v4 MODE0 input)
    #pragma unroll
    for (int fm = 0; fm < 2; fm++)
        #pragma unroll
        for (int hh = 0; hh < 2; hh++){
            float inv = 1.f / l_[fm][hh];
            int sg = qb*256 + w*32 + fm*16 + rr + 8*hh;
            float* Op = O + ((size_t)b*S_LEN + sg)*D_DIM + hd*DH;
            int j0 = cb*2, j1 = cb*2 + 1;
            int p0 = ((j0 & 3) << 1) | (j0 >> 2);
            int p1 = ((j1 & 3) << 1) | (j1 >> 2);
            #pragma unroll
            for (int fn = 0; fn < 8; fn++){
                Op[fn*8 + p0] = tfr(o[fm][fn][hh*2]   * inv);
                Op[fn*8 + p1] = tfr(o[fm][fn][hh*2+1] * inv);
            }
        }
}

extern "C" void kernel_launch(void* const* d_in, const int* in_sizes, int n_in,
                              void* d_out, int out_size)
{
    const float* X  = (const float*)d_in[0];
    const float* Wq = (const float*)d_in[1];
    const float* bq = (const float*)d_in[2];
    const float* Wk = (const float*)d_in[3];
    const float* bk = (const float*)d_in[4];
    const float* Wv = (const float*)d_in[5];
    const float* bv = (const float*)d_in[6];
    const float* Wo = (const float*)d_in[7];
    const float* bo = (const float*)d_in[8];
    float* out = (float*)d_out;

    float *gq, *gk, *gv, *gh, *gxp, *gwp;
    cudaGetSymbolAddress((void**)&gq, g_Q);
    cudaGetSymbolAddress((void**)&gk, g_K);
    cudaGetSymbolAddress((void**)&gv, g_V);
    cudaGetSymbolAddress((void**)&gh, g_H);
    cudaGetSymbolAddress((void**)&gxp, g_Xp);
    cudaGetSymbolAddress((void**)&gwp, g_Wp);

    const int gsmem = 4*24576;                                   // 98304 B
    cudaFuncSetAttribute(gemm_v4<0>, cudaFuncAttributeMaxDynamicSharedMemorySize, gsmem);
    cudaFuncSetAttribute(gemm_v4<1>, cudaFuncAttributeMaxDynamicSharedMemorySize, gsmem);
    cudaFuncSetAttribute(gemm_v4<2>, cudaFuncAttributeMaxDynamicSharedMemorySize, gsmem);
    const int attn_smem = (4*4608 + 256*72)*(int)sizeof(unsigned);  // 147456 B
    cudaFuncSetAttribute(attn_v3, cudaFuncAttributeMaxDynamicSharedMemorySize, attn_smem);

    rope_table_kernel<<<(S_LEN*512 + 255)/256, 256>>>();

    const int WG = D_DIM*D_DIM/8;   // 131072 groups per weight
    conv_perm<<<(M_TOT*D_DIM/8 + 255)/256, 256>>>(X, gxp, M_TOT*D_DIM/8);
    conv_perm<<<(WG + 255)/256, 256>>>(Wq, gwp + 0*D_DIM*D_DIM, WG);
    conv_perm<<<(WG + 255)/256, 256>>>(Wk, gwp + 1*D_DIM*D_DIM, WG);
    conv_perm<<<(WG + 255)/256, 256>>>(Wv, gwp + 2*D_DIM*D_DIM, WG);
    conv_perm<<<(WG + 255)/256, 256>>>(Wo, gwp + 3*D_DIM*D_DIM, WG);

    dim3 ggrid(D_DIM/128, M_TOT/128);   // (8, 64)
    gemm_v4<2><<<ggrid, 128, gsmem>>>(gxp, gwp + 0*D_DIM*D_DIM, bq, gq);
    gemm_v4<2><<<ggrid, 128, gsmem>>>(gxp, gwp + 1*D_DIM*D_DIM, bk, gk);
    gemm_v4<1><<<ggrid, 128, gsmem>>>(gxp, gwp + 2*D_DIM*D_DIM, bv, gv);

    attn_v3<<<dim3(S_LEN/256, NH, BATCH), 256, attn_smem>>>(gq, gk, gv, gh);

    gemm_v4<0><<<ggrid, 128, gsmem>>>(gh, gwp + 3*D_DIM*D_DIM, bo, out);
}

// round 7
// speedup vs baseline: 1.1838x; 1.1838x over previous
#include <cuda_runtime.h>
#include <math.h>
#include <stdint.h>

#define BATCH 4
#define S_LEN 2048
#define D_DIM 1024
#define NH    16
#define DH    64
#define M_TOT (BATCH*S_LEN)

__device__ float  g_Q[BATCH*NH*S_LEN*DH];
__device__ float  g_K[BATCH*NH*S_LEN*DH];
__device__ float  g_V[BATCH*NH*S_LEN*DH];
__device__ float  g_H[M_TOT*D_DIM];
__device__ float2 g_tab[S_LEN*(D_DIM/2)];

__device__ __forceinline__ unsigned f2tf(float x){
    unsigned u; asm("cvt.rna.tf32.f32 %0, %1;" : "=r"(u) : "f"(x)); return u;
}
__device__ __forceinline__ void mma8(float* c, const unsigned* a, const unsigned* b){
    asm volatile("mma.sync.aligned.m16n8k8.row.col.f32.tf32.tf32.f32 "
        "{%0,%1,%2,%3}, {%4,%5,%6,%7}, {%8,%9}, {%0,%1,%2,%3};"
        : "+f"(c[0]), "+f"(c[1]), "+f"(c[2]), "+f"(c[3])
        : "r"(a[0]), "r"(a[1]), "r"(a[2]), "r"(a[3]), "r"(b[0]), "r"(b[1]));
}

__global__ void rope_table_kernel(){
    int idx = blockIdx.x*blockDim.x + threadIdx.x;
    if (idx >= S_LEN*512) return;
    int s = idx >> 9, p = idx & 511;
    double inv = exp(-((double)(2*p)/(double)D_DIM)*log(10000.0));
    float sn, cs; sincosf((float)s*(float)inv, &sn, &cs);
    g_tab[idx] = make_float2(cs, sn);
}

// ============ GEMM v5: out = A[M,1024] @ W[N,1024]^T + bias ============
// 4 warps, warp 64x64, CTA 128x128. Double-buffered, register-staged.
// smem row layout (words): [pair0..3 of group0 (8w)][pad 4][pairs of group1][pad 4] = 24w.
// Pair j of group g = (k: g*8+j, k+4). Fragment loads are LDS.64, all conflict-free.
template<int MODE>
__global__ __launch_bounds__(128,2) void gemm_v5(
    const float* __restrict__ A, const float* __restrict__ W,
    const float* __restrict__ bias, float* __restrict__ out)
{
    extern __shared__ unsigned sm5[];   // [2 buf][A:3072 | B:3072]
    int tid = threadIdx.x, lane = tid & 31, w = tid >> 5;
    int rr = lane >> 2, cb = lane & 3;
    int wm = (w >> 1)*64, wn = (w & 1)*64;
    int m0 = blockIdx.y*128, n0 = blockIdx.x*128;

    float acc[4][8][4];
    #pragma unroll
    for (int i=0;i<4;i++)
        #pragma unroll
        for (int j=0;j<8;j++)
            #pragma unroll
            for (int e=0;e<4;e++) acc[i][j][e] = 0.f;

    int row0 = tid >> 1, g0 = tid & 1;
    const float* Ar0 = A + (size_t)(m0+row0)*D_DIM + g0*8;
    const float* Ar1 = Ar0 + (size_t)64*D_DIM;
    const float* Wr0 = W + (size_t)(n0+row0)*D_DIM + g0*8;
    const float* Wr1 = Wr0 + (size_t)64*D_DIM;
    unsigned* pA0 = sm5 + row0*24 + g0*12;          // + buf*6144
    unsigned* pA1 = pA0 + 64*24;
    unsigned* pB0 = pA0 + 3072;
    unsigned* pB1 = pA1 + 3072;

    float4 a0q0, a0q1, a1q0, a1q1, b0q0, b0q1, b1q0, b1q1;

    // prologue: chunk 0
    a0q0 = *(const float4*)(Ar0);     a0q1 = *(const float4*)(Ar0+4);
    a1q0 = *(const float4*)(Ar1);     a1q1 = *(const float4*)(Ar1+4);
    b0q0 = *(const float4*)(Wr0);     b0q1 = *(const float4*)(Wr0+4);
    b1q0 = *(const float4*)(Wr1);     b1q1 = *(const float4*)(Wr1+4);
    *(uint4*)(pA0)   = make_uint4(f2tf(a0q0.x),f2tf(a0q1.x),f2tf(a0q0.y),f2tf(a0q1.y));
    *(uint4*)(pA0+4) = make_uint4(f2tf(a0q0.z),f2tf(a0q1.z),f2tf(a0q0.w),f2tf(a0q1.w));
    *(uint4*)(pA1)   = make_uint4(f2tf(a1q0.x),f2tf(a1q1.x),f2tf(a1q0.y),f2tf(a1q1.y));
    *(uint4*)(pA1+4) = make_uint4(f2tf(a1q0.z),f2tf(a1q1.z),f2tf(a1q0.w),f2tf(a1q1.w));
    *(uint4*)(pB0)   = make_uint4(f2tf(b0q0.x),f2tf(b0q1.x),f2tf(b0q0.y),f2tf(b0q1.y));
    *(uint4*)(pB0+4) = make_uint4(f2tf(b0q0.z),f2tf(b0q1.z),f2tf(b0q0.w),f2tf(b0q1.w));
    *(uint4*)(pB1)   = make_uint4(f2tf(b1q0.x),f2tf(b1q1.x),f2tf(b1q0.y),f2tf(b1q1.y));
    *(uint4*)(pB1+4) = make_uint4(f2tf(b1q0.z),f2tf(b1q1.z),f2tf(b1q0.w),f2tf(b1q1.w));
    __syncthreads();

    for (int it = 0; it < 64; it++){
        int cur = it & 1;
        if (it + 1 < 64){
            int k0 = (it+1)*16;
            a0q0 = *(const float4*)(Ar0+k0);  a0q1 = *(const float4*)(Ar0+k0+4);
            a1q0 = *(const float4*)(Ar1+k0);  a1q1 = *(const float4*)(Ar1+k0+4);
            b0q0 = *(const float4*)(Wr0+k0);  b0q1 = *(const float4*)(Wr0+k0+4);
            b1q0 = *(const float4*)(Wr1+k0);  b1q1 = *(const float4*)(Wr1+k0+4);
        }
        const unsigned* Sa = sm5 + cur*6144;
        const unsigned* Sb = Sa + 3072;
        #pragma unroll
        for (int ks = 0; ks < 2; ks++){
            int co = ks*12 + cb*2;
            unsigned a[4][4], b[8][2];
            #pragma unroll
            for (int fm = 0; fm < 4; fm++){
                int r = wm + rr + 16*fm;
                uint2 l0 = *(const uint2*)&Sa[r*24 + co];
                uint2 l1 = *(const uint2*)&Sa[(r+8)*24 + co];
                a[fm][0]=l0.x; a[fm][1]=l1.x; a[fm][2]=l0.y; a[fm][3]=l1.y;
            }
            #pragma unroll
            for (int fn = 0; fn < 8; fn++){
                uint2 l = *(const uint2*)&Sb[(wn + rr + 8*fn)*24 + co];
                b[fn][0]=l.x; b[fn][1]=l.y;
            }
            #pragma unroll
            for (int fm = 0; fm < 4; fm++)
                #pragma unroll
                for (int fn = 0; fn < 8; fn++)
                    mma8(acc[fm][fn], a[fm], b[fn]);
        }
        if (it + 1 < 64){
            unsigned* dA0 = sm5 + (cur^1)*6144 + row0*24 + g0*12;
            unsigned* dA1 = dA0 + 64*24;
            unsigned* dB0 = dA0 + 3072;
            unsigned* dB1 = dA1 + 3072;
            *(uint4*)(dA0)   = make_uint4(f2tf(a0q0.x),f2tf(a0q1.x),f2tf(a0q0.y),f2tf(a0q1.y));
            *(uint4*)(dA0+4) = make_uint4(f2tf(a0q0.z),f2tf(a0q1.z),f2tf(a0q0.w),f2tf(a0q1.w));
            *(uint4*)(dA1)   = make_uint4(f2tf(a1q0.x),f2tf(a1q1.x),f2tf(a1q0.y),f2tf(a1q1.y));
            *(uint4*)(dA1+4) = make_uint4(f2tf(a1q0.z),f2tf(a1q1.z),f2tf(a1q0.w),f2tf(a1q1.w));
            *(uint4*)(dB0)   = make_uint4(f2tf(b0q0.x),f2tf(b0q1.x),f2tf(b0q0.y),f2tf(b0q1.y));
            *(uint4*)(dB0+4) = make_uint4(f2tf(b0q0.z),f2tf(b0q1.z),f2tf(b0q0.w),f2tf(b0q1.w));
            *(uint4*)(dB1)   = make_uint4(f2tf(b1q0.x),f2tf(b1q1.x),f2tf(b1q0.y),f2tf(b1q1.y));
            *(uint4*)(dB1+4) = make_uint4(f2tf(b1q0.z),f2tf(b1q1.z),f2tf(b1q0.w),f2tf(b1q1.w));
            __syncthreads();
        }
    }

    #pragma unroll
    for (int fn = 0; fn < 8; fn++){
        int colg = n0 + wn + fn*8 + cb*2;
        float b0v = bias[colg], b1v = bias[colg+1];
        #pragma unroll
        for (int fm = 0; fm < 4; fm++){
            #pragma unroll
            for (int half = 0; half < 2; half++){
                int m = m0 + wm + fm*16 + rr + half*8;
                float v0 = acc[fm][fn][half*2+0] + b0v;
                float v1 = acc[fm][fn][half*2+1] + b1v;
                int srow = m & (S_LEN-1);
                if (MODE == 2){
                    float2 cs = g_tab[srow*512 + (colg >> 1)];
                    float e = v0*cs.x - v1*cs.y;
                    float d = v0*cs.y + v1*cs.x;
                    v0 = e; v1 = d;
                }
                if (MODE == 0){
                    *(float2*)(out + (size_t)m*D_DIM + colg) = make_float2(v0, v1);
                } else {
                    int bb = m >> 11, hh = colg >> 6, dd = colg & 63;
                    *(float2*)(out + ((size_t)(bb*NH+hh)*S_LEN + srow)*DH + dd) = make_float2(v0, v1);
                }
            }
        }
    }
}

// ============ Flash attention (R5, verbatim) ============
__global__ __launch_bounds__(256,1) void attn_v3(
    const float* __restrict__ Q, const float* __restrict__ K,
    const float* __restrict__ V, float* __restrict__ O)
{
    extern __shared__ unsigned sm[];
    int tid = threadIdx.x, lane = tid & 31, w = tid >> 5;
    int rr = lane >> 2, cb = lane & 3;
    int qb = blockIdx.x, hd = blockIdx.y, b = blockIdx.z;

    const float* Qp = Q + ((size_t)(b*NH + hd)*S_LEN + qb*256 + w*32)*DH;
    const float* Kp = K + (size_t)(b*NH + hd)*S_LEN*DH;
    const float* Vp = V + (size_t)(b*NH + hd)*S_LEN*DH;
    unsigned* Pw = sm + 18432 + (w*32)*72;

    unsigned q[2][8][4];
    #pragma unroll
    for (int fm = 0; fm < 2; fm++){
        int r0 = fm*16 + rr;
        #pragma unroll
        for (int ks = 0; ks < 8; ks++){
            int c = ks*8 + cb;
            q[fm][ks][0] = f2tf(0.125f * Qp[(size_t)r0*DH + c]);
            q[fm][ks][1] = f2tf(0.125f * Qp[(size_t)(r0+8)*DH + c]);
            q[fm][ks][2] = f2tf(0.125f * Qp[(size_t)r0*DH + c+4]);
            q[fm][ks][3] = f2tf(0.125f * Qp[(size_t)(r0+8)*DH + c+4]);
        }
    }

    float m_[2][2], l_[2][2], o[2][8][4];
    #pragma unroll
    for (int fm=0;fm<2;fm++)
        #pragma unroll
        for (int hh=0;hh<2;hh++){ m_[fm][hh] = -1e30f; l_[fm][hh] = 0.f; }
    #pragma unroll
    for (int fm=0;fm<2;fm++)
        #pragma unroll
        for (int fn=0;fn<8;fn++)
            #pragma unroll
            for (int e=0;e<4;e++) o[fm][fn][e] = 0.f;

    float4 kst[4], vst[4];
    #pragma unroll
    for (int l=0;l<4;l++){ int slot = tid + l*256; int kp = slot>>4, cq = slot&15;
        kst[l] = *(const float4*)(Kp + (size_t)kp*DH + cq*4);
        vst[l] = *(const float4*)(Vp + (size_t)kp*DH + cq*4); }
    #pragma unroll
    for (int l=0;l<4;l++){ int slot = tid + l*256; int kp = slot>>4, cq = slot&15;
        const float* kv = (const float*)&kst[l];
        const float* vv = (const float*)&vst[l];
        #pragma unroll
        for (int j=0;j<4;j++){
            sm[(cq*4+j)*72 + ((kp + 2*cq) & 63)] = f2tf(kv[j]);
            sm[9216 + kp*72 + ((cq*4+j + 2*(kp>>2)) & 63)] = f2tf(vv[j]); } }
    __syncthreads();

    for (int t = 0; t < 32; t++){
        int cur = t & 1;
        const unsigned* Kc = sm + cur*4608;
        const unsigned* Vc = sm + 9216 + cur*4608;
        if (t + 1 < 32){
            const float* Kn = Kp + (size_t)(t+1)*64*DH;
            const float* Vn = Vp + (size_t)(t+1)*64*DH;
            #pragma unroll
            for (int l=0;l<4;l++){ int slot = tid + l*256; int kp = slot>>4, cq = slot&15;
                kst[l] = *(const float4*)(Kn + (size_t)kp*DH + cq*4);
                vst[l] = *(const float4*)(Vn + (size_t)kp*DH + cq*4); }
        }

        float s[2][8][4];
        #pragma unroll
        for (int fm=0;fm<2;fm++)
            #pragma unroll
            for (int fn=0;fn<8;fn++)
                #pragma unroll
                for (int e=0;e<4;e++) s[fm][fn][e] = 0.f;

        #pragma unroll
        for (int ks = 0; ks < 8; ks++){
            int c1 = ks*8 + cb;
            #pragma unroll
            for (int fn = 0; fn < 8; fn++){
                int n = fn*8 + rr;
                unsigned bb[2];
                bb[0] = Kc[c1*72 + ((n + 4*ks) & 63)];
                bb[1] = Kc[(c1+4)*72 + ((n + 4*ks + 2) & 63)];
                mma8(s[0][fn], q[0][ks], bb);
                mma8(s[1][fn], q[1][ks], bb);
            }
        }

        #pragma unroll
        for (int fm = 0; fm < 2; fm++)
            #pragma unroll
            for (int hh = 0; hh < 2; hh++){
                float rm = -1e30f;
                #pragma unroll
                for (int fn = 0; fn < 8; fn++)
                    rm = fmaxf(rm, fmaxf(s[fm][fn][hh*2], s[fm][fn][hh*2+1]));
                rm = fmaxf(rm, __shfl_xor_sync(0xffffffffu, rm, 1));
                rm = fmaxf(rm, __shfl_xor_sync(0xffffffffu, rm, 2));
                float mn = fmaxf(m_[fm][hh], rm);
                float sum = 0.f;
                #pragma unroll
                for (int fn = 0; fn < 8; fn++){
                    s[fm][fn][hh*2]   = __expf(s[fm][fn][hh*2]   - mn);
                    s[fm][fn][hh*2+1] = __expf(s[fm][fn][hh*2+1] - mn);
                    sum += s[fm][fn][hh*2] + s[fm][fn][hh*2+1];
                }
                sum += __shfl_xor_sync(0xffffffffu, sum, 1);
                sum += __shfl_xor_sync(0xffffffffu, sum, 2);
                float alpha = __expf(m_[fm][hh] - mn);
                l_[fm][hh] = l_[fm][hh]*alpha + sum;
                m_[fm][hh] = mn;
                #pragma unroll
                for (int fn = 0; fn < 8; fn++){
                    o[fm][fn][hh*2]   *= alpha;
                    o[fm][fn][hh*2+1] *= alpha;
                }
            }

        #pragma unroll
        for (int fm = 0; fm < 2; fm++)
            #pragma unroll
            for (int hh = 0; hh < 2; hh++){
                int rl = fm*16 + rr + 8*hh;
                int ro = 4*(rl>>2);
                #pragma unroll
                for (int fn = 0; fn < 8; fn++){
                    int pc = fn*8 + cb*2;
                    *(uint2*)&Pw[rl*72 + ((pc + ro) & 63)] =
                        make_uint2(f2tf(s[fm][fn][hh*2]), f2tf(s[fm][fn][hh*2+1]));
                }
            }
        __syncwarp();

        #pragma unroll
        for (int ks = 0; ks < 8; ks++){
            int kc = ks*8 + cb;
            unsigned a[2][4];
            #pragma unroll
            for (int fm = 0; fm < 2; fm++){
                int r0 = fm*16 + rr, r1 = r0 + 8;
                a[fm][0] = Pw[r0*72 + ((kc + 4*(r0>>2)) & 63)];
                a[fm][1] = Pw[r1*72 + ((kc + 4*(r1>>2)) & 63)];
                a[fm][2] = Pw[r0*72 + ((kc + 4 + 4*(r0>>2)) & 63)];
                a[fm][3] = Pw[r1*72 + ((kc + 4 + 4*(r1>>2)) & 63)];
            }
            #pragma unroll
            for (int fn = 0; fn < 8; fn++){
                int n = fn*8 + rr;
                unsigned bb[2];
                bb[0] = Vc[kc*72 + ((n + 4*ks) & 63)];
                bb[1] = Vc[(kc+4)*72 + ((n + 4*ks + 2) & 63)];
                mma8(o[0][fn], a[0], bb);
                mma8(o[1][fn], a[1], bb);
            }
        }

        __syncthreads();
        if (t + 1 < 32){
            unsigned* Kw = sm + (cur^1)*4608;
            unsigned* Vw = sm + 9216 + (cur^1)*4608;
            #pragma unroll
            for (int l=0;l<4;l++){ int slot = tid + l*256; int kp = slot>>4, cq = slot&15;
                const float* kv = (const float*)&kst[l];
                const float* vv = (const float*)&vst[l];
                #pragma unroll
                for (int j=0;j<4;j++){
                    Kw[(cq*4+j)*72 + ((kp + 2*cq) & 63)] = f2tf(kv[j]);
                    Vw[kp*72 + ((cq*4+j + 2*(kp>>2)) & 63)] = f2tf(vv[j]); } }
            __syncthreads();
        }
    }

    #pragma unroll
    for (int fm = 0; fm < 2; fm++)
        #pragma unroll
        for (int hh = 0; hh < 2; hh++){
            float inv = 1.f / l_[fm][hh];
            int sg = qb*256 + w*32 + fm*16 + rr + 8*hh;
            float* Op = O + ((size_t)b*S_LEN + sg)*D_DIM + hd*DH;
            #pragma unroll
            for (int fn = 0; fn < 8; fn++){
                int col = fn*8 + cb*2;
                *(float2*)(Op + col) =
                    make_float2(o[fm][fn][hh*2]*inv, o[fm][fn][hh*2+1]*inv);
            }
        }
}

extern "C" void kernel_launch(void* const* d_in, const int* in_sizes, int n_in,
                              void* d_out, int out_size)
{
    const float* X  = (const float*)d_in[0];
    const float* Wq = (const float*)d_in[1];
    const float* bq = (const float*)d_in[2];
    const float* Wk = (const float*)d_in[3];
    const float* bk = (const float*)d_in[4];
    const float* Wv = (const float*)d_in[5];
    const float* bv = (const float*)d_in[6];
    const float* Wo = (const float*)d_in[7];
    const float* bo = (const float*)d_in[8];
    float* out = (float*)d_out;

    float *gq, *gk, *gv, *gh;
    cudaGetSymbolAddress((void**)&gq, g_Q);
    cudaGetSymbolAddress((void**)&gk, g_K);
    cudaGetSymbolAddress((void**)&gv, g_V);
    cudaGetSymbolAddress((void**)&gh, g_H);

    const int gsmem = 2*6144*(int)sizeof(unsigned);   // 49152 B
    cudaFuncSetAttribute(gemm_v5<0>, cudaFuncAttributeMaxDynamicSharedMemorySize, gsmem);
    cudaFuncSetAttribute(gemm_v5<1>, cudaFuncAttributeMaxDynamicSharedMemorySize, gsmem);
    cudaFuncSetAttribute(gemm_v5<2>, cudaFuncAttributeMaxDynamicSharedMemorySize, gsmem);
    const int attn_smem = (4*4608 + 256*72)*(int)sizeof(unsigned);  // 147456 B
    cudaFuncSetAttribute(attn_v3, cudaFuncAttributeMaxDynamicSharedMemorySize, attn_smem);

    rope_table_kernel<<<(S_LEN*512 + 255)/256, 256>>>();

    dim3 ggrid(D_DIM/128, M_TOT/128);   // (8, 64)
    gemm_v5<2><<<ggrid, 128, gsmem>>>(X, Wq, bq, gq);
    gemm_v5<2><<<ggrid, 128, gsmem>>>(X, Wk, bk, gk);
    gemm_v5<1><<<ggrid, 128, gsmem>>>(X, Wv, bv, gv);

    attn_v3<<<dim3(S_LEN/256, NH, BATCH), 256, attn_smem>>>(gq, gk, gv, gh);

    gemm_v5<0><<<ggrid, 128, gsmem>>>(gh, Wo, bo, out);
}

// round 8
// speedup vs baseline: 1.2333x; 1.0419x over previous
#include <cuda_runtime.h>
#include <math.h>
#include <stdint.h>

#define BATCH 4
#define S_LEN 2048
#define D_DIM 1024
#define NH    16
#define DH    64
#define M_TOT (BATCH*S_LEN)

__device__ float  g_Q[BATCH*NH*S_LEN*DH];
__device__ float  g_K[BATCH*NH*S_LEN*DH];
__device__ float  g_V[BATCH*NH*S_LEN*DH];
__device__ float  g_H[M_TOT*D_DIM];
__device__ float  g_Xp[M_TOT*D_DIM];      // pre-rounded X; reused for pre-rounded H
__device__ float  g_Wp[4*D_DIM*D_DIM];    // pre-rounded Wq,Wk,Wv,Wo
__device__ float2 g_tab[S_LEN*(D_DIM/2)];

__device__ __forceinline__ unsigned f2tf(float x){
    unsigned u; asm("cvt.rna.tf32.f32 %0, %1;" : "=r"(u) : "f"(x)); return u;
}
__device__ __forceinline__ float tfr(float x){ return __uint_as_float(f2tf(x)); }
__device__ __forceinline__ void mma8(float* c, const unsigned* a, const unsigned* b){
    asm volatile("mma.sync.aligned.m16n8k8.row.col.f32.tf32.tf32.f32 "
        "{%0,%1,%2,%3}, {%4,%5,%6,%7}, {%8,%9}, {%0,%1,%2,%3};"
        : "+f"(c[0]), "+f"(c[1]), "+f"(c[2]), "+f"(c[3])
        : "r"(a[0]), "r"(a[1]), "r"(a[2]), "r"(a[3]), "r"(b[0]), "r"(b[1]));
}

__global__ void rope_table_kernel(){
    int idx = blockIdx.x*blockDim.x + threadIdx.x;
    if (idx >= S_LEN*512) return;
    int s = idx >> 9, p = idx & 511;
    double inv = exp(-((double)(2*p)/(double)D_DIM)*log(10000.0));
    float sn, cs; sincosf((float)s*(float)inv, &sn, &cs);
    g_tab[idx] = make_float2(cs, sn);
}

__global__ void conv_tf32(const float* __restrict__ src, float* __restrict__ dst, int n4){
    int i = blockIdx.x*blockDim.x + threadIdx.x;
    if (i >= n4) return;
    float4 v = ((const float4*)src)[i];
    ((float4*)dst)[i] = make_float4(tfr(v.x), tfr(v.y), tfr(v.z), tfr(v.w));
}

// ============ GEMM (R5 structure): out = A[M,1024] @ W[N,1024]^T + bias ============
// Inputs pre-tf32-rounded; smem fills are raw copies. 4 warps, warp 64x64.
// smem: S[c][ (col + 8*(c>>2)) & 127 ], stride 136 words.
// MODE 0: plain fp32 [M,N]; MODE 1: rounded scatter [B,H,S,dh]; MODE 2: RoPE+round+scatter
template<int MODE>
__global__ __launch_bounds__(128,2) void gemm_v6(
    const float* __restrict__ A, const float* __restrict__ W,
    const float* __restrict__ bias, float* __restrict__ out)
{
    __shared__ unsigned As[2][16*136], Bs[2][16*136];
    int tid = threadIdx.x, lane = tid & 31, w = tid >> 5;
    int rr = lane >> 2, cb = lane & 3;
    int wm = (w >> 1) * 64, wn = (w & 1) * 64;
    int m0 = blockIdx.y * 128, n0 = blockIdx.x * 128;

    float acc[4][8][4];
    #pragma unroll
    for (int i=0;i<4;i++)
        #pragma unroll
        for (int j=0;j<8;j++)
            #pragma unroll
            for (int e=0;e<4;e++) acc[i][j][e] = 0.f;

    float4 av[4], bv[4];
    #pragma unroll
    for (int l=0;l<4;l++){ int slot = tid + l*128; int m = slot>>2, kq = slot&3;
        av[l] = *(const float4*)(A + (size_t)(m0+m)*D_DIM + kq*4);
        bv[l] = *(const float4*)(W + (size_t)(n0+m)*D_DIM + kq*4); }
    #pragma unroll
    for (int l=0;l<4;l++){ int slot = tid + l*128; int m = slot>>2, kq = slot&3;
        const float* a4 = (const float*)&av[l];
        const float* b4 = (const float*)&bv[l];
        #pragma unroll
        for (int j=0;j<4;j++){
            As[0][(kq*4+j)*136 + ((m + 8*kq) & 127)] = __float_as_uint(a4[j]);
            Bs[0][(kq*4+j)*136 + ((m + 8*kq) & 127)] = __float_as_uint(b4[j]); } }
    __syncthreads();

    for (int it = 0; it < 64; it++){
        int cur = it & 1;
        if (it + 1 < 64){
            int k0 = (it+1)*16;
            #pragma unroll
            for (int l=0;l<4;l++){ int slot = tid + l*128; int m = slot>>2, kq = slot&3;
                av[l] = *(const float4*)(A + (size_t)(m0+m)*D_DIM + k0 + kq*4);
                bv[l] = *(const float4*)(W + (size_t)(n0+m)*D_DIM + k0 + kq*4); }
        }
        #pragma unroll
        for (int ks = 0; ks < 2; ks++){
            int c1 = ks*8 + cb, off = 16*ks;
            unsigned a[4][4], b[8][2];
            #pragma unroll
            for (int fm = 0; fm < 4; fm++){
                int r = wm + rr + fm*16;
                a[fm][0] = As[cur][c1*136 + ((r + off) & 127)];
                a[fm][1] = As[cur][c1*136 + ((r + 8 + off) & 127)];
                a[fm][2] = As[cur][(c1+4)*136 + ((r + off + 8) & 127)];
                a[fm][3] = As[cur][(c1+4)*136 + ((r + 8 + off + 8) & 127)];
            }
            #pragma unroll
            for (int fn = 0; fn < 8; fn++){
                int n = wn + rr + fn*8;
                b[fn][0] = Bs[cur][c1*136 + ((n + off) & 127)];
                b[fn][1] = Bs[cur][(c1+4)*136 + ((n + off + 8) & 127)];
            }
            #pragma unroll
            for (int fm = 0; fm < 4; fm++)
                #pragma unroll
                for (int fn = 0; fn < 8; fn++)
                    mma8(acc[fm][fn], a[fm], b[fn]);
        }
        if (it + 1 < 64){
            int nxt = cur ^ 1;
            #pragma unroll
            for (int l=0;l<4;l++){ int slot = tid + l*128; int m = slot>>2, kq = slot&3;
                const float* a4 = (const float*)&av[l];
                const float* b4 = (const float*)&bv[l];
                #pragma unroll
                for (int j=0;j<4;j++){
                    As[nxt][(kq*4+j)*136 + ((m + 8*kq) & 127)] = __float_as_uint(a4[j]);
                    Bs[nxt][(kq*4+j)*136 + ((m + 8*kq) & 127)] = __float_as_uint(b4[j]); } }
            __syncthreads();
        }
    }

    #pragma unroll
    for (int fn = 0; fn < 8; fn++){
        int colg = n0 + wn + fn*8 + cb*2;
        float b0v = bias[colg], b1v = bias[colg+1];
        #pragma unroll
        for (int fm = 0; fm < 4; fm++){
            #pragma unroll
            for (int half = 0; half < 2; half++){
                int m = m0 + wm + fm*16 + rr + half*8;
                float v0 = acc[fm][fn][half*2+0] + b0v;
                float v1 = acc[fm][fn][half*2+1] + b1v;
                int srow = m & (S_LEN-1);
                if (MODE == 2){
                    float2 cs = g_tab[srow*512 + (colg >> 1)];
                    float e = v0*cs.x - v1*cs.y;
                    float d = v0*cs.y + v1*cs.x;
                    v0 = e; v1 = d;
                }
                if (MODE == 0){
                    *(float2*)(out + (size_t)m*D_DIM + colg) = make_float2(v0, v1);
                } else {
                    int bb = m >> 11, hh = colg >> 6, dd = colg & 63;
                    *(float2*)(out + ((size_t)(bb*NH+hh)*S_LEN + srow)*DH + dd) =
                        make_float2(tfr(v0), tfr(v1));   // pre-round for attention
                }
            }
        }
    }
}

// ============ Flash attention (R5; Q/K/V arrive tf32-pre-rounded) ============
__global__ __launch_bounds__(256,1) void attn_v3(
    const float* __restrict__ Q, const float* __restrict__ K,
    const float* __restrict__ V, float* __restrict__ O)
{
    extern __shared__ unsigned sm[];
    int tid = threadIdx.x, lane = tid & 31, w = tid >> 5;
    int rr = lane >> 2, cb = lane & 3;
    int qb = blockIdx.x, hd = blockIdx.y, b = blockIdx.z;

    const float* Qp = Q + ((size_t)(b*NH + hd)*S_LEN + qb*256 + w*32)*DH;
    const float* Kp = K + (size_t)(b*NH + hd)*S_LEN*DH;
    const float* Vp = V + (size_t)(b*NH + hd)*S_LEN*DH;
    unsigned* Pw = sm + 18432 + (w*32)*72;

    unsigned q[2][8][4];
    #pragma unroll
    for (int fm = 0; fm < 2; fm++){
        int r0 = fm*16 + rr;
        #pragma unroll
        for (int ks = 0; ks < 8; ks++){
            int c = ks*8 + cb;
            q[fm][ks][0] = __float_as_uint(0.125f * Qp[(size_t)r0*DH + c]);
            q[fm][ks][1] = __float_as_uint(0.125f * Qp[(size_t)(r0+8)*DH + c]);
            q[fm][ks][2] = __float_as_uint(0.125f * Qp[(size_t)r0*DH + c+4]);
            q[fm][ks][3] = __float_as_uint(0.125f * Qp[(size_t)(r0+8)*DH + c+4]);
        }
    }

    float m_[2][2], l_[2][2], o[2][8][4];
    #pragma unroll
    for (int fm=0;fm<2;fm++)
        #pragma unroll
        for (int hh=0;hh<2;hh++){ m_[fm][hh] = -1e30f; l_[fm][hh] = 0.f; }
    #pragma unroll
    for (int fm=0;fm<2;fm++)
        #pragma unroll
        for (int fn=0;fn<8;fn++)
            #pragma unroll
            for (int e=0;e<4;e++) o[fm][fn][e] = 0.f;

    float4 kst[4], vst[4];
    #pragma unroll
    for (int l=0;l<4;l++){ int slot = tid + l*256; int kp = slot>>4, cq = slot&15;
        kst[l] = *(const float4*)(Kp + (size_t)kp*DH + cq*4);
        vst[l] = *(const float4*)(Vp + (size_t)kp*DH + cq*4); }
    #pragma unroll
    for (int l=0;l<4;l++){ int slot = tid + l*256; int kp = slot>>4, cq = slot&15;
        const float* kv = (const float*)&kst[l];
        const float* vv = (const float*)&vst[l];
        #pragma unroll
        for (int j=0;j<4;j++){
            sm[(cq*4+j)*72 + ((kp + 2*cq) & 63)] = __float_as_uint(kv[j]);
            sm[9216 + kp*72 + ((cq*4+j + 2*(kp>>2)) & 63)] = __float_as_uint(vv[j]); } }
    __syncthreads();

    for (int t = 0; t < 32; t++){
        int cur = t & 1;
        const unsigned* Kc = sm + cur*4608;
        const unsigned* Vc = sm + 9216 + cur*4608;
        if (t + 1 < 32){
            const float* Kn = Kp + (size_t)(t+1)*64*DH;
            const float* Vn = Vp + (size_t)(t+1)*64*DH;
            #pragma unroll
            for (int l=0;l<4;l++){ int slot = tid + l*256; int kp = slot>>4, cq = slot&15;
                kst[l] = *(const float4*)(Kn + (size_t)kp*DH + cq*4);
                vst[l] = *(const float4*)(Vn + (size_t)kp*DH + cq*4); }
        }

        float s[2][8][4];
        #pragma unroll
        for (int fm=0;fm<2;fm++)
            #pragma unroll
            for (int fn=0;fn<8;fn++)
                #pragma unroll
                for (int e=0;e<4;e++) s[fm][fn][e] = 0.f;

        #pragma unroll
        for (int ks = 0; ks < 8; ks++){
            int c1 = ks*8 + cb;
            #pragma unroll
            for (int fn = 0; fn < 8; fn++){
                int n = fn*8 + rr;
                unsigned bb[2];
                bb[0] = Kc[c1*72 + ((n + 4*ks) & 63)];
                bb[1] = Kc[(c1+4)*72 + ((n + 4*ks + 2) & 63)];
                mma8(s[0][fn], q[0][ks], bb);
                mma8(s[1][fn], q[1][ks], bb);
            }
        }

        #pragma unroll
        for (int fm = 0; fm < 2; fm++)
            #pragma unroll
            for (int hh = 0; hh < 2; hh++){
                float rm = -1e30f;
                #pragma unroll
                for (int fn = 0; fn < 8; fn++)
                    rm = fmaxf(rm, fmaxf(s[fm][fn][hh*2], s[fm][fn][hh*2+1]));
                rm = fmaxf(rm, __shfl_xor_sync(0xffffffffu, rm, 1));
                rm = fmaxf(rm, __shfl_xor_sync(0xffffffffu, rm, 2));
                float mn = fmaxf(m_[fm][hh], rm);
                float sum = 0.f;
                #pragma unroll
                for (int fn = 0; fn < 8; fn++){
                    s[fm][fn][hh*2]   = __expf(s[fm][fn][hh*2]   - mn);
                    s[fm][fn][hh*2+1] = __expf(s[fm][fn][hh*2+1] - mn);
                    sum += s[fm][fn][hh*2] + s[fm][fn][hh*2+1];
                }
                sum += __shfl_xor_sync(0xffffffffu, sum, 1);
                sum += __shfl_xor_sync(0xffffffffu, sum, 2);
                float alpha = __expf(m_[fm][hh] - mn);
                l_[fm][hh] = l_[fm][hh]*alpha + sum;
                m_[fm][hh] = mn;
                #pragma unroll
                for (int fn = 0; fn < 8; fn++){
                    o[fm][fn][hh*2]   *= alpha;
                    o[fm][fn][hh*2+1] *= alpha;
                }
            }

        #pragma unroll
        for (int fm = 0; fm < 2; fm++)
            #pragma unroll
            for (int hh = 0; hh < 2; hh++){
                int rl = fm*16 + rr + 8*hh;
                int ro = 4*(rl>>2);
                #pragma unroll
                for (int fn = 0; fn < 8; fn++){
                    int pc = fn*8 + cb*2;
                    *(uint2*)&Pw[rl*72 + ((pc + ro) & 63)] =
                        make_uint2(f2tf(s[fm][fn][hh*2]), f2tf(s[fm][fn][hh*2+1]));
                }
            }
        __syncwarp();

        #pragma unroll
        for (int ks = 0; ks < 8; ks++){
            int kc = ks*8 + cb;
            unsigned a[2][4];
            #pragma unroll
            for (int fm = 0; fm < 2; fm++){
                int r0 = fm*16 + rr, r1 = r0 + 8;
                a[fm][0] = Pw[r0*72 + ((kc + 4*(r0>>2)) & 63)];
                a[fm][1] = Pw[r1*72 + ((kc + 4*(r1>>2)) & 63)];
                a[fm][2] = Pw[r0*72 + ((kc + 4 + 4*(r0>>2)) & 63)];
                a[fm][3] = Pw[r1*72 + ((kc + 4 + 4*(r1>>2)) & 63)];
            }
            #pragma unroll
            for (int fn = 0; fn < 8; fn++){
                int n = fn*8 + rr;
                unsigned bb[2];
                bb[0] = Vc[kc*72 + ((n + 4*ks) & 63)];
                bb[1] = Vc[(kc+4)*72 + ((n + 4*ks + 2) & 63)];
                mma8(o[0][fn], a[0], bb);
                mma8(o[1][fn], a[1], bb);
            }
        }

        __syncthreads();
        if (t + 1 < 32){
            unsigned* Kw = sm + (cur^1)*4608;
            unsigned* Vw = sm + 9216 + (cur^1)*4608;
            #pragma unroll
            for (int l=0;l<4;l++){ int slot = tid + l*256; int kp = slot>>4, cq = slot&15;
                const float* kv = (const float*)&kst[l];
                const float* vv = (const float*)&vst[l];
                #pragma unroll
                for (int j=0;j<4;j++){
                    Kw[(cq*4+j)*72 + ((kp + 2*cq) & 63)] = __float_as_uint(kv[j]);
                    Vw[kp*72 + ((cq*4+j + 2*(kp>>2)) & 63)] = __float_as_uint(vv[j]); } }
            __syncthreads();
        }
    }

    #pragma unroll
    for (int fm = 0; fm < 2; fm++)
        #pragma unroll
        for (int hh = 0; hh < 2; hh++){
            float inv = 1.f / l_[fm][hh];
            int sg = qb*256 + w*32 + fm*16 + rr + 8*hh;
            float* Op = O + ((size_t)b*S_LEN + sg)*D_DIM + hd*DH;
            #pragma unroll
            for (int fn = 0; fn < 8; fn++){
                int col = fn*8 + cb*2;
                *(float2*)(Op + col) =
                    make_float2(o[fm][fn][hh*2]*inv, o[fm][fn][hh*2+1]*inv);
            }
        }
}

extern "C" void kernel_launch(void* const* d_in, const int* in_sizes, int n_in,
                              void* d_out, int out_size)
{
    const float* X  = (const float*)d_in[0];
    const float* Wq = (const float*)d_in[1];
    const float* bq = (const float*)d_in[2];
    const float* Wk = (const float*)d_in[3];
    const float* bk = (const float*)d_in[4];
    const float* Wv = (const float*)d_in[5];
    const float* bv = (const float*)d_in[6];
    const float* Wo = (const float*)d_in[7];
    const float* bo = (const float*)d_in[8];
    float* out = (float*)d_out;

    float *gq, *gk, *gv, *gh, *gxp, *gwp;
    cudaGetSymbolAddress((void**)&gq, g_Q);
    cudaGetSymbolAddress((void**)&gk, g_K);
    cudaGetSymbolAddress((void**)&gv, g_V);
    cudaGetSymbolAddress((void**)&gh, g_H);
    cudaGetSymbolAddress((void**)&gxp, g_Xp);
    cudaGetSymbolAddress((void**)&gwp, g_Wp);

    const int attn_smem = (4*4608 + 256*72)*(int)sizeof(unsigned);  // 147456 B
    cudaFuncSetAttribute(attn_v3, cudaFuncAttributeMaxDynamicSharedMemorySize, attn_smem);

    rope_table_kernel<<<(S_LEN*512 + 255)/256, 256>>>();

    const int X4 = M_TOT*D_DIM/4, W4 = D_DIM*D_DIM/4;
    conv_tf32<<<(X4 + 255)/256, 256>>>(X, gxp, X4);
    conv_tf32<<<(W4 + 255)/256, 256>>>(Wq, gwp + 0*D_DIM*D_DIM, W4);
    conv_tf32<<<(W4 + 255)/256, 256>>>(Wk, gwp + 1*D_DIM*D_DIM, W4);
    conv_tf32<<<(W4 + 255)/256, 256>>>(Wv, gwp + 2*D_DIM*D_DIM, W4);
    conv_tf32<<<(W4 + 255)/256, 256>>>(Wo, gwp + 3*D_DIM*D_DIM, W4);

    dim3 ggrid(D_DIM/128, M_TOT/128);   // (8, 64)
    gemm_v6<2><<<ggrid, 128>>>(gxp, gwp + 0*D_DIM*D_DIM, bq, gq);
    gemm_v6<2><<<ggrid, 128>>>(gxp, gwp + 1*D_DIM*D_DIM, bk, gk);
    gemm_v6<1><<<ggrid, 128>>>(gxp, gwp + 2*D_DIM*D_DIM, bv, gv);

    attn_v3<<<dim3(S_LEN/256, NH, BATCH), 256, attn_smem>>>(gq, gk, gv, gh);

    conv_tf32<<<(X4 + 255)/256, 256>>>(gh, gxp, X4);   // pre-round H (reuse X buffer)
    gemm_v6<0><<<ggrid, 128>>>(gxp, gwp + 3*D_DIM*D_DIM, bo, out);
}

// round 9
// speedup vs baseline: 1.9457x; 1.5776x over previous
#include <cuda_runtime.h>
#include <cuda_fp16.h>
#include <math.h>
#include <stdint.h>

#define BATCH 4
#define S_LEN 2048
#define D_DIM 1024
#define NH    16
#define DH    64
#define M_TOT (BATCH*S_LEN)

__device__ __half g_Qh[BATCH*NH*S_LEN*DH];
__device__ __half g_Kh[BATCH*NH*S_LEN*DH];
__device__ __half g_VTh[BATCH*NH*DH*S_LEN];   // [b,h][dh][S]
__device__ __half g_Hh[M_TOT*D_DIM];
__device__ __half g_Xh[M_TOT*D_DIM];
__device__ __half g_Wh[4*D_DIM*D_DIM];
__device__ float2 g_tab[S_LEN*(D_DIM/2)];

__device__ __forceinline__ unsigned pk(float a, float b){
    __half2 h = __floats2half2_rn(a, b); return *(unsigned*)&h;
}
__device__ __forceinline__ void mma16(float* c, const unsigned* a, const unsigned* b){
    asm volatile("mma.sync.aligned.m16n8k16.row.col.f32.f16.f16.f32 "
        "{%0,%1,%2,%3}, {%4,%5,%6,%7}, {%8,%9}, {%0,%1,%2,%3};"
        : "+f"(c[0]), "+f"(c[1]), "+f"(c[2]), "+f"(c[3])
        : "r"(a[0]), "r"(a[1]), "r"(a[2]), "r"(a[3]), "r"(b[0]), "r"(b[1]));
}

__global__ void rope_table_kernel(){
    int idx = blockIdx.x*blockDim.x + threadIdx.x;
    if (idx >= S_LEN*512) return;
    int s = idx >> 9, p = idx & 511;
    double inv = exp(-((double)(2*p)/(double)D_DIM)*log(10000.0));
    float sn, cs; sincosf((float)s*(float)inv, &sn, &cs);
    g_tab[idx] = make_float2(cs, sn);
}

__global__ void conv_f16(const float* __restrict__ src, __half* __restrict__ dst, int n8){
    int i = blockIdx.x*blockDim.x + threadIdx.x;
    if (i >= n8) return;
    const float4* s = (const float4*)src + (size_t)i*2;
    float4 v0 = s[0], v1 = s[1];
    uint4 o;
    o.x = pk(v0.x, v0.y); o.y = pk(v0.z, v0.w);
    o.z = pk(v1.x, v1.y); o.w = pk(v1.z, v1.w);
    ((uint4*)dst)[i] = o;
}

// ============ fp16 GEMM: out = A[M,1024] @ W[N,1024]^T + bias ============
// 4 warps, warp 64x64, CTA 128x128, chunk k16 = 8 half2-words, double-buffered.
// smem: S[kw][(col + 8*(kw>>2)) & 127], stride 136 words.
// MODE 0: fp32 [M,N]+bias; MODE 2: RoPE+half scatter [B,H,S,dh]; MODE 3: half scatter transposed [B,H,dh,S]
template<int MODE>
__global__ __launch_bounds__(128,2) void gemm_h(
    const __half* __restrict__ A, const __half* __restrict__ W,
    const float* __restrict__ bias, void* __restrict__ outv)
{
    __shared__ unsigned As[2][8*136], Bs[2][8*136];
    int tid = threadIdx.x, lane = tid & 31, w = tid >> 5;
    int rr = lane >> 2, cb = lane & 3;
    int wm = (w >> 1)*64, wn = (w & 1)*64;
    int m0 = blockIdx.y*128, n0 = blockIdx.x*128;

    float acc[4][8][4];
    #pragma unroll
    for (int i=0;i<4;i++)
        #pragma unroll
        for (int j=0;j<8;j++)
            #pragma unroll
            for (int e=0;e<4;e++) acc[i][j][e] = 0.f;

    int m = (tid + 0) >> 1;              // slot l: m = (tid+l*128)>>1, kq = slot&1
    const uint4* Ar[2]; const uint4* Wr[2];
    int mm[2], kk[2];
    #pragma unroll
    for (int l=0;l<2;l++){
        int slot = tid + l*128;
        mm[l] = slot >> 1; kk[l] = slot & 1;
        Ar[l] = (const uint4*)A + (size_t)(m0+mm[l])*128;
        Wr[l] = (const uint4*)W + (size_t)(n0+mm[l])*128;
    }
    (void)m;

    uint4 av[2], bv[2];
    #pragma unroll
    for (int l=0;l<2;l++){ av[l] = Ar[l][kk[l]]; bv[l] = Wr[l][kk[l]]; }
    #pragma unroll
    for (int l=0;l<2;l++){
        const unsigned* a4 = (const unsigned*)&av[l];
        const unsigned* b4 = (const unsigned*)&bv[l];
        #pragma unroll
        for (int j=0;j<4;j++){
            As[0][(kk[l]*4+j)*136 + ((mm[l] + 8*kk[l]) & 127)] = a4[j];
            Bs[0][(kk[l]*4+j)*136 + ((mm[l] + 8*kk[l]) & 127)] = b4[j];
        }
    }
    __syncthreads();

    for (int it = 0; it < 64; it++){
        int cur = it & 1;
        if (it + 1 < 64){
            #pragma unroll
            for (int l=0;l<2;l++){
                av[l] = Ar[l][(it+1)*2 + kk[l]];
                bv[l] = Wr[l][(it+1)*2 + kk[l]];
            }
        }
        unsigned a[4][4], b[8][2];
        #pragma unroll
        for (int fm = 0; fm < 4; fm++){
            int r = wm + rr + fm*16;
            a[fm][0] = As[cur][cb*136 + (r & 127)];
            a[fm][1] = As[cur][cb*136 + ((r+8) & 127)];
            a[fm][2] = As[cur][(cb+4)*136 + ((r+8) & 127)];
            a[fm][3] = As[cur][(cb+4)*136 + ((r+16) & 127)];
        }
        #pragma unroll
        for (int fn = 0; fn < 8; fn++){
            int n = wn + rr + fn*8;
            b[fn][0] = Bs[cur][cb*136 + (n & 127)];
            b[fn][1] = Bs[cur][(cb+4)*136 + ((n+8) & 127)];
        }
        #pragma unroll
        for (int fm = 0; fm < 4; fm++)
            #pragma unroll
            for (int fn = 0; fn < 8; fn++)
                mma16(acc[fm][fn], a[fm], b[fn]);
        if (it + 1 < 64){
            int nxt = cur ^ 1;
            #pragma unroll
            for (int l=0;l<2;l++){
                const unsigned* a4 = (const unsigned*)&av[l];
                const unsigned* b4 = (const unsigned*)&bv[l];
                #pragma unroll
                for (int j=0;j<4;j++){
                    As[nxt][(kk[l]*4+j)*136 + ((mm[l] + 8*kk[l]) & 127)] = a4[j];
                    Bs[nxt][(kk[l]*4+j)*136 + ((mm[l] + 8*kk[l]) & 127)] = b4[j];
                }
            }
            __syncthreads();
        }
    }

    #pragma unroll
    for (int fn = 0; fn < 8; fn++){
        int colg = n0 + wn + fn*8 + cb*2;
        float b0v = bias[colg], b1v = bias[colg+1];
        #pragma unroll
        for (int fm = 0; fm < 4; fm++){
            #pragma unroll
            for (int half = 0; half < 2; half++){
                int mr = m0 + wm + fm*16 + rr + half*8;
                float v0 = acc[fm][fn][half*2+0] + b0v;
                float v1 = acc[fm][fn][half*2+1] + b1v;
                int srow = mr & (S_LEN-1);
                int bb = mr >> 11, hh = colg >> 6, dd = colg & 63;
                if (MODE == 2){
                    float2 cs = g_tab[srow*512 + (colg >> 1)];
                    float e = v0*cs.x - v1*cs.y;
                    float d = v0*cs.y + v1*cs.x;
                    v0 = e; v1 = d;
                }
                if (MODE == 0){
                    *(float2*)((float*)outv + (size_t)mr*D_DIM + colg) = make_float2(v0, v1);
                } else if (MODE == 2){
                    ((unsigned*)outv)[((size_t)(bb*NH+hh)*S_LEN + srow)*32 + (dd>>1)] = pk(v0, v1);
                } else {  // MODE 3: V transposed [b,h][dh][S]
                    __half* ov = (__half*)outv + ((size_t)(bb*NH+hh)*DH + dd)*S_LEN + srow;
                    ov[0] = __float2half(v0);
                    ov[S_LEN] = __float2half(v1);
                }
            }
        }
    }
}

// ============ fp16 flash attention: 8 warps x 32q x 64k ============
// K smem: Ks[kpos][kw] stride 36; VT smem: Vs[dh][kw] stride 36; P: Pw[row][kw] stride 36.
__global__ __launch_bounds__(256,1) void attn_h(
    const __half* __restrict__ Q, const __half* __restrict__ K,
    const __half* __restrict__ VT, __half* __restrict__ H)
{
    extern __shared__ unsigned sm[];
    // layout (words): K: [0, 2*2304), V: [4608, +2*2304), P: [9216, +9216)
    int tid = threadIdx.x, lane = tid & 31, w = tid >> 5;
    int rr = lane >> 2, cb = lane & 3;
    int qb = blockIdx.x, hd = blockIdx.y, b = blockIdx.z;
    int bh = b*NH + hd;

    const unsigned* Qw = (const unsigned*)(Q + ((size_t)bh*S_LEN + qb*256 + w*32)*DH);
    const uint4* Kg = (const uint4*)(K + (size_t)bh*S_LEN*DH);
    const uint4* Vg = (const uint4*)(VT + (size_t)bh*DH*S_LEN);
    unsigned* Pw = sm + 9216 + (w*32)*36;

    const unsigned sc = 0x30003000u;  // half2(0.125, 0.125)
    unsigned q[2][4][4];
    #pragma unroll
    for (int fm = 0; fm < 2; fm++){
        int r0 = fm*16 + rr;
        #pragma unroll
        for (int ks = 0; ks < 4; ks++){
            int kw = ks*8 + cb;
            unsigned u0 = Qw[r0*32 + kw],     u1 = Qw[(r0+8)*32 + kw];
            unsigned u2 = Qw[r0*32 + kw + 4], u3 = Qw[(r0+8)*32 + kw + 4];
            __half2 s2 = *(__half2*)&sc;
            __half2 h0 = __hmul2(*(__half2*)&u0, s2), h1 = __hmul2(*(__half2*)&u1, s2);
            __half2 h2 = __hmul2(*(__half2*)&u2, s2), h3 = __hmul2(*(__half2*)&u3, s2);
            q[fm][ks][0] = *(unsigned*)&h0; q[fm][ks][1] = *(unsigned*)&h1;
            q[fm][ks][2] = *(unsigned*)&h2; q[fm][ks][3] = *(unsigned*)&h3;
        }
    }

    float m_[2][2], l_[2][2], o[2][8][4];
    #pragma unroll
    for (int fm=0;fm<2;fm++)
        #pragma unroll
        for (int hh=0;hh<2;hh++){ m_[fm][hh] = -1e30f; l_[fm][hh] = 0.f; }
    #pragma unroll
    for (int fm=0;fm<2;fm++)
        #pragma unroll
        for (int fn=0;fn<8;fn++)
            #pragma unroll
            for (int e=0;e<4;e++) o[fm][fn][e] = 0.f;

    uint4 kst[2], vst[2];
    int kp_[2], cq_[2];
    #pragma unroll
    for (int l=0;l<2;l++){ int slot = tid + l*256; kp_[l] = slot>>3; cq_[l] = slot&7; }

    // prologue tile 0
    #pragma unroll
    for (int l=0;l<2;l++){
        kst[l] = Kg[(size_t)kp_[l]*8 + cq_[l]];            // K row kp (8 uint4/row)
        vst[l] = Vg[(size_t)kp_[l]*256 + cq_[l]];          // VT row dh=kp (256 uint4/row)
    }
    #pragma unroll
    for (int l=0;l<2;l++){
        *(uint4*)&sm[kp_[l]*36 + cq_[l]*4] = kst[l];
        *(uint4*)&sm[4608 + kp_[l]*36 + cq_[l]*4] = vst[l];
    }
    __syncthreads();

    for (int t = 0; t < 32; t++){
        int cur = t & 1;
        const unsigned* Kc = sm + cur*2304;
        const unsigned* Vc = sm + 4608 + cur*2304;
        if (t + 1 < 32){
            #pragma unroll
            for (int l=0;l<2;l++){
                kst[l] = Kg[(size_t)((t+1)*64 + kp_[l])*8 + cq_[l]];
                vst[l] = Vg[(size_t)kp_[l]*256 + (t+1)*8 + cq_[l]];
            }
        }

        float s[2][8][4];
        #pragma unroll
        for (int fm=0;fm<2;fm++)
            #pragma unroll
            for (int fn=0;fn<8;fn++)
                #pragma unroll
                for (int e=0;e<4;e++) s[fm][fn][e] = 0.f;

        #pragma unroll
        for (int ks = 0; ks < 4; ks++){
            int kw = ks*8 + cb;
            #pragma unroll
            for (int fn = 0; fn < 8; fn++){
                int n = fn*8 + rr;
                unsigned bb[2];
                bb[0] = Kc[n*36 + kw];
                bb[1] = Kc[n*36 + kw + 4];
                mma16(s[0][fn], q[0][ks], bb);
                mma16(s[1][fn], q[1][ks], bb);
            }
        }

        #pragma unroll
        for (int fm = 0; fm < 2; fm++)
            #pragma unroll
            for (int hh = 0; hh < 2; hh++){
                float rm = -1e30f;
                #pragma unroll
                for (int fn = 0; fn < 8; fn++)
                    rm = fmaxf(rm, fmaxf(s[fm][fn][hh*2], s[fm][fn][hh*2+1]));
                rm = fmaxf(rm, __shfl_xor_sync(0xffffffffu, rm, 1));
                rm = fmaxf(rm, __shfl_xor_sync(0xffffffffu, rm, 2));
                float mn = fmaxf(m_[fm][hh], rm);
                float sum = 0.f;
                #pragma unroll
                for (int fn = 0; fn < 8; fn++){
                    s[fm][fn][hh*2]   = __expf(s[fm][fn][hh*2]   - mn);
                    s[fm][fn][hh*2+1] = __expf(s[fm][fn][hh*2+1] - mn);
                    sum += s[fm][fn][hh*2] + s[fm][fn][hh*2+1];
                }
                sum += __shfl_xor_sync(0xffffffffu, sum, 1);
                sum += __shfl_xor_sync(0xffffffffu, sum, 2);
                float alpha = __expf(m_[fm][hh] - mn);
                l_[fm][hh] = l_[fm][hh]*alpha + sum;
                m_[fm][hh] = mn;
                #pragma unroll
                for (int fn = 0; fn < 8; fn++){
                    o[fm][fn][hh*2]   *= alpha;
                    o[fm][fn][hh*2+1] *= alpha;
                }
            }

        #pragma unroll
        for (int fm = 0; fm < 2; fm++)
            #pragma unroll
            for (int hh = 0; hh < 2; hh++){
                int rl = fm*16 + rr + 8*hh;
                #pragma unroll
                for (int fn = 0; fn < 8; fn++)
                    Pw[rl*36 + fn*4 + cb] = pk(s[fm][fn][hh*2], s[fm][fn][hh*2+1]);
            }
        __syncwarp();

        #pragma unroll
        for (int ks = 0; ks < 4; ks++){
            int kw = ks*8 + cb;
            unsigned a[2][4];
            #pragma unroll
            for (int fm = 0; fm < 2; fm++){
                int r0 = fm*16 + rr;
                a[fm][0] = Pw[r0*36 + kw];
                a[fm][1] = Pw[(r0+8)*36 + kw];
                a[fm][2] = Pw[r0*36 + kw + 4];
                a[fm][3] = Pw[(r0+8)*36 + kw + 4];
            }
            #pragma unroll
            for (int fn = 0; fn < 8; fn++){
                int n = fn*8 + rr;
                unsigned bb[2];
                bb[0] = Vc[n*36 + kw];
                bb[1] = Vc[n*36 + kw + 4];
                mma16(o[0][fn], a[0], bb);
                mma16(o[1][fn], a[1], bb);
            }
        }

        __syncthreads();
        if (t + 1 < 32){
            int nxt = (cur^1)*2304;
            #pragma unroll
            for (int l=0;l<2;l++){
                *(uint4*)&sm[nxt + kp_[l]*36 + cq_[l]*4] = kst[l];
                *(uint4*)&sm[4608 + nxt + kp_[l]*36 + cq_[l]*4] = vst[l];
            }
            __syncthreads();
        }
    }

    unsigned* Hw = (unsigned*)H;
    #pragma unroll
    for (int fm = 0; fm < 2; fm++)
        #pragma unroll
        for (int hh = 0; hh < 2; hh++){
            float inv = 1.f / l_[fm][hh];
            int sg = qb*256 + w*32 + fm*16 + rr + 8*hh;
            size_t base = ((size_t)b*S_LEN + sg)*512 + hd*32;
            #pragma unroll
            for (int fn = 0; fn < 8; fn++)
                Hw[base + fn*4 + cb] = pk(o[fm][fn][hh*2]*inv, o[fm][fn][hh*2+1]*inv);
        }
}

extern "C" void kernel_launch(void* const* d_in, const int* in_sizes, int n_in,
                              void* d_out, int out_size)
{
    const float* X  = (const float*)d_in[0];
    const float* Wq = (const float*)d_in[1];
    const float* bq = (const float*)d_in[2];
    const float* Wk = (const float*)d_in[3];
    const float* bk = (const float*)d_in[4];
    const float* Wv = (const float*)d_in[5];
    const float* bv = (const float*)d_in[6];
    const float* Wo = (const float*)d_in[7];
    const float* bo = (const float*)d_in[8];
    float* out = (float*)d_out;

    __half *gq, *gk, *gvt, *gh, *gx, *gw;
    cudaGetSymbolAddress((void**)&gq, g_Qh);
    cudaGetSymbolAddress((void**)&gk, g_Kh);
    cudaGetSymbolAddress((void**)&gvt, g_VTh);
    cudaGetSymbolAddress((void**)&gh, g_Hh);
    cudaGetSymbolAddress((void**)&gx, g_Xh);
    cudaGetSymbolAddress((void**)&gw, g_Wh);

    const int attn_smem = 18432*4;   // 73728 B
    cudaFuncSetAttribute(attn_h, cudaFuncAttributeMaxDynamicSharedMemorySize, attn_smem);

    rope_table_kernel<<<(S_LEN*512 + 255)/256, 256>>>();

    const int X8 = M_TOT*D_DIM/8, W8 = D_DIM*D_DIM/8;
    conv_f16<<<(X8 + 255)/256, 256>>>(X, gx, X8);
    conv_f16<<<(W8 + 255)/256, 256>>>(Wq, gw + 0*D_DIM*D_DIM, W8);
    conv_f16<<<(W8 + 255)/256, 256>>>(Wk, gw + 1*D_DIM*D_DIM, W8);
    conv_f16<<<(W8 + 255)/256, 256>>>(Wv, gw + 2*D_DIM*D_DIM, W8);
    conv_f16<<<(W8 + 255)/256, 256>>>(Wo, gw + 3*D_DIM*D_DIM, W8);

    dim3 ggrid(D_DIM/128, M_TOT/128);   // (8, 64)
    gemm_h<2><<<ggrid, 128>>>(gx, gw + 0*D_DIM*D_DIM, bq, gq);
    gemm_h<2><<<ggrid, 128>>>(gx, gw + 1*D_DIM*D_DIM, bk, gk);
    gemm_h<3><<<ggrid, 128>>>(gx, gw + 2*D_DIM*D_DIM, bv, gvt);

    attn_h<<<dim3(S_LEN/256, NH, BATCH), 256, attn_smem>>>(gq, gk, gvt, gh);

    gemm_h<0><<<ggrid, 128>>>(gh, gw + 3*D_DIM*D_DIM, bo, out);
}

// round 10
// speedup vs baseline: 2.0035x; 1.0297x over previous
#include <cuda_runtime.h>
#include <cuda_fp16.h>
#include <math.h>
#include <stdint.h>

#define BATCH 4
#define S_LEN 2048
#define D_DIM 1024
#define NH    16
#define DH    64
#define M_TOT (BATCH*S_LEN)

__device__ __half g_Qh[BATCH*NH*S_LEN*DH];
__device__ __half g_Kh[BATCH*NH*S_LEN*DH];
__device__ __half g_VTh[BATCH*NH*DH*S_LEN];   // [b,h][dh][S]
__device__ __half g_Hh[M_TOT*D_DIM];
__device__ __half g_Xh[M_TOT*D_DIM];
__device__ __half g_Wh[4*D_DIM*D_DIM];
__device__ float2 g_tab[S_LEN*(D_DIM/2)];

__device__ __forceinline__ unsigned pk(float a, float b){
    __half2 h = __floats2half2_rn(a, b); return *(unsigned*)&h;
}
__device__ __forceinline__ void mma16(float* c, const unsigned* a, const unsigned* b){
    asm volatile("mma.sync.aligned.m16n8k16.row.col.f32.f16.f16.f32 "
        "{%0,%1,%2,%3}, {%4,%5,%6,%7}, {%8,%9}, {%0,%1,%2,%3};"
        : "+f"(c[0]), "+f"(c[1]), "+f"(c[2]), "+f"(c[3])
        : "r"(a[0]), "r"(a[1]), "r"(a[2]), "r"(a[3]), "r"(b[0]), "r"(b[1]));
}

__global__ void rope_table_kernel(){
    int idx = blockIdx.x*blockDim.x + threadIdx.x;
    if (idx >= S_LEN*512) return;
    int s = idx >> 9, p = idx & 511;
    double inv = exp(-((double)(2*p)/(double)D_DIM)*log(10000.0));
    float sn, cs; sincosf((float)s*(float)inv, &sn, &cs);
    g_tab[idx] = make_float2(cs, sn);
}

__global__ void conv_f16(const float* __restrict__ src, __half* __restrict__ dst, int n8){
    int i = blockIdx.x*blockDim.x + threadIdx.x;
    if (i >= n8) return;
    const float4* s = (const float4*)src + (size_t)i*2;
    float4 v0 = s[0], v1 = s[1];
    uint4 o;
    o.x = pk(v0.x, v0.y); o.y = pk(v0.z, v0.w);
    o.z = pk(v1.x, v1.y); o.w = pk(v1.z, v1.w);
    ((uint4*)dst)[i] = o;
}

// ============ fp16 GEMM: out = A[M,1024] @ W[N,1024]^T + bias ============
// 4 warps, warp 64x64, CTA 128x128, chunk k16 = 8 half2-words, double-buffered.
// MODE 0: fp32 [M,N]+bias; MODE 2: RoPE+half scatter [B,H,S,dh]; MODE 3: half scatter transposed [B,H,dh,S]
template<int MODE>
__global__ __launch_bounds__(128,2) void gemm_h(
    const __half* __restrict__ A, const __half* __restrict__ W,
    const float* __restrict__ bias, void* __restrict__ outv)
{
    __shared__ unsigned As[2][8*136], Bs[2][8*136];
    int tid = threadIdx.x, lane = tid & 31, w = tid >> 5;
    int rr = lane >> 2, cb = lane & 3;
    int wm = (w >> 1)*64, wn = (w & 1)*64;
    int m0 = blockIdx.y*128, n0 = blockIdx.x*128;

    float acc[4][8][4];
    #pragma unroll
    for (int i=0;i<4;i++)
        #pragma unroll
        for (int j=0;j<8;j++)
            #pragma unroll
            for (int e=0;e<4;e++) acc[i][j][e] = 0.f;

    const uint4* Ar[2]; const uint4* Wr[2];
    int mm[2], kk[2];
    #pragma unroll
    for (int l=0;l<2;l++){
        int slot = tid + l*128;
        mm[l] = slot >> 1; kk[l] = slot & 1;
        Ar[l] = (const uint4*)A + (size_t)(m0+mm[l])*128;
        Wr[l] = (const uint4*)W + (size_t)(n0+mm[l])*128;
    }

    uint4 av[2], bv[2];
    #pragma unroll
    for (int l=0;l<2;l++){ av[l] = Ar[l][kk[l]]; bv[l] = Wr[l][kk[l]]; }
    #pragma unroll
    for (int l=0;l<2;l++){
        const unsigned* a4 = (const unsigned*)&av[l];
        const unsigned* b4 = (const unsigned*)&bv[l];
        #pragma unroll
        for (int j=0;j<4;j++){
            As[0][(kk[l]*4+j)*136 + ((mm[l] + 8*kk[l]) & 127)] = a4[j];
            Bs[0][(kk[l]*4+j)*136 + ((mm[l] + 8*kk[l]) & 127)] = b4[j];
        }
    }
    __syncthreads();

    for (int it = 0; it < 64; it++){
        int cur = it & 1;
        if (it + 1 < 64){
            #pragma unroll
            for (int l=0;l<2;l++){
                av[l] = Ar[l][(it+1)*2 + kk[l]];
                bv[l] = Wr[l][(it+1)*2 + kk[l]];
            }
        }
        unsigned a[4][4], b[8][2];
        #pragma unroll
        for (int fm = 0; fm < 4; fm++){
            int r = wm + rr + fm*16;
            a[fm][0] = As[cur][cb*136 + (r & 127)];
            a[fm][1] = As[cur][cb*136 + ((r+8) & 127)];
            a[fm][2] = As[cur][(cb+4)*136 + ((r+8) & 127)];
            a[fm][3] = As[cur][(cb+4)*136 + ((r+16) & 127)];
        }
        #pragma unroll
        for (int fn = 0; fn < 8; fn++){
            int n = wn + rr + fn*8;
            b[fn][0] = Bs[cur][cb*136 + (n & 127)];
            b[fn][1] = Bs[cur][(cb+4)*136 + ((n+8) & 127)];
        }
        #pragma unroll
        for (int fm = 0; fm < 4; fm++)
            #pragma unroll
            for (int fn = 0; fn < 8; fn++)
                mma16(acc[fm][fn], a[fm], b[fn]);
        if (it + 1 < 64){
            int nxt = cur ^ 1;
            #pragma unroll
            for (int l=0;l<2;l++){
                const unsigned* a4 = (const unsigned*)&av[l];
                const unsigned* b4 = (const unsigned*)&bv[l];
                #pragma unroll
                for (int j=0;j<4;j++){
                    As[nxt][(kk[l]*4+j)*136 + ((mm[l] + 8*kk[l]) & 127)] = a4[j];
                    Bs[nxt][(kk[l]*4+j)*136 + ((mm[l] + 8*kk[l]) & 127)] = b4[j];
                }
            }
            __syncthreads();
        }
    }

    #pragma unroll
    for (int fn = 0; fn < 8; fn++){
        int colg = n0 + wn + fn*8 + cb*2;
        float b0v = bias[colg], b1v = bias[colg+1];
        #pragma unroll
        for (int fm = 0; fm < 4; fm++){
            #pragma unroll
            for (int half = 0; half < 2; half++){
                int mr = m0 + wm + fm*16 + rr + half*8;
                float v0 = acc[fm][fn][half*2+0] + b0v;
                float v1 = acc[fm][fn][half*2+1] + b1v;
                int srow = mr & (S_LEN-1);
                int bb = mr >> 11, hh = colg >> 6, dd = colg & 63;
                if (MODE == 2){
                    float2 cs = g_tab[srow*512 + (colg >> 1)];
                    float e = v0*cs.x - v1*cs.y;
                    float d = v0*cs.y + v1*cs.x;
                    v0 = e; v1 = d;
                }
                if (MODE == 0){
                    *(float2*)((float*)outv + (size_t)mr*D_DIM + colg) = make_float2(v0, v1);
                } else if (MODE == 2){
                    ((unsigned*)outv)[((size_t)(bb*NH+hh)*S_LEN + srow)*32 + (dd>>1)] = pk(v0, v1);
                } else {  // MODE 3: V transposed [b,h][dh][S]
                    __half* ov = (__half*)outv + ((size_t)(bb*NH+hh)*DH + dd)*S_LEN + srow;
                    ov[0] = __float2half(v0);
                    ov[S_LEN] = __float2half(v1);
                }
            }
        }
    }
}

// ============ fp16 flash attention: 8 warps x 32q x 64k, register-resident P ============
// K smem: Ks[kpos][kw] stride 36; VT smem: Vs[dh][kw] stride 36. One barrier per tile.
__global__ __launch_bounds__(256,1) void attn_h(
    const __half* __restrict__ Q, const __half* __restrict__ K,
    const __half* __restrict__ VT, __half* __restrict__ H)
{
    extern __shared__ unsigned sm[];
    // layout (words): K: [0, 2*2304), V: [4608, +2*2304)
    int tid = threadIdx.x, lane = tid & 31, w = tid >> 5;
    int rr = lane >> 2, cb = lane & 3;
    int qb = blockIdx.x, hd = blockIdx.y, b = blockIdx.z;
    int bh = b*NH + hd;

    const unsigned* Qw = (const unsigned*)(Q + ((size_t)bh*S_LEN + qb*256 + w*32)*DH);
    const uint4* Kg = (const uint4*)(K + (size_t)bh*S_LEN*DH);
    const uint4* Vg = (const uint4*)(VT + (size_t)bh*DH*S_LEN);

    const unsigned sc = 0x30003000u;  // half2(0.125, 0.125)
    unsigned q[2][4][4];
    #pragma unroll
    for (int fm = 0; fm < 2; fm++){
        int r0 = fm*16 + rr;
        #pragma unroll
        for (int ks = 0; ks < 4; ks++){
            int kw = ks*8 + cb;
            unsigned u0 = Qw[r0*32 + kw],     u1 = Qw[(r0+8)*32 + kw];
            unsigned u2 = Qw[r0*32 + kw + 4], u3 = Qw[(r0+8)*32 + kw + 4];
            __half2 s2 = *(__half2*)&sc;
            __half2 h0 = __hmul2(*(__half2*)&u0, s2), h1 = __hmul2(*(__half2*)&u1, s2);
            __half2 h2 = __hmul2(*(__half2*)&u2, s2), h3 = __hmul2(*(__half2*)&u3, s2);
            q[fm][ks][0] = *(unsigned*)&h0; q[fm][ks][1] = *(unsigned*)&h1;
            q[fm][ks][2] = *(unsigned*)&h2; q[fm][ks][3] = *(unsigned*)&h3;
        }
    }

    float m_[2][2], l_[2][2], o[2][8][4];
    #pragma unroll
    for (int fm=0;fm<2;fm++)
        #pragma unroll
        for (int hh=0;hh<2;hh++){ m_[fm][hh] = -1e30f; l_[fm][hh] = 0.f; }
    #pragma unroll
    for (int fm=0;fm<2;fm++)
        #pragma unroll
        for (int fn=0;fn<8;fn++)
            #pragma unroll
            for (int e=0;e<4;e++) o[fm][fn][e] = 0.f;

    uint4 kst[2], vst[2];
    int kp_[2], cq_[2];
    #pragma unroll
    for (int l=0;l<2;l++){ int slot = tid + l*256; kp_[l] = slot>>3; cq_[l] = slot&7; }

    // prologue tile 0
    #pragma unroll
    for (int l=0;l<2;l++){
        kst[l] = Kg[(size_t)kp_[l]*8 + cq_[l]];
        vst[l] = Vg[(size_t)kp_[l]*256 + cq_[l]];
    }
    #pragma unroll
    for (int l=0;l<2;l++){
        *(uint4*)&sm[kp_[l]*36 + cq_[l]*4] = kst[l];
        *(uint4*)&sm[4608 + kp_[l]*36 + cq_[l]*4] = vst[l];
    }
    __syncthreads();

    for (int t = 0; t < 32; t++){
        int cur = t & 1;
        const unsigned* Kc = sm + cur*2304;
        const unsigned* Vc = sm + 4608 + cur*2304;
        if (t + 1 < 32){
            #pragma unroll
            for (int l=0;l<2;l++){
                kst[l] = Kg[(size_t)((t+1)*64 + kp_[l])*8 + cq_[l]];
                vst[l] = Vg[(size_t)kp_[l]*256 + (t+1)*8 + cq_[l]];
            }
        }

        float s[2][8][4];
        #pragma unroll
        for (int fm=0;fm<2;fm++)
            #pragma unroll
            for (int fn=0;fn<8;fn++)
                #pragma unroll
                for (int e=0;e<4;e++) s[fm][fn][e] = 0.f;

        #pragma unroll
        for (int ks = 0; ks < 4; ks++){
            int kw = ks*8 + cb;
            #pragma unroll
            for (int fn = 0; fn < 8; fn++){
                int n = fn*8 + rr;
                unsigned bb[2];
                bb[0] = Kc[n*36 + kw];
                bb[1] = Kc[n*36 + kw + 4];
                mma16(s[0][fn], q[0][ks], bb);
                mma16(s[1][fn], q[1][ks], bb);
            }
        }

        #pragma unroll
        for (int fm = 0; fm < 2; fm++)
            #pragma unroll
            for (int hh = 0; hh < 2; hh++){
                float rm = -1e30f;
                #pragma unroll
                for (int fn = 0; fn < 8; fn++)
                    rm = fmaxf(rm, fmaxf(s[fm][fn][hh*2], s[fm][fn][hh*2+1]));
                rm = fmaxf(rm, __shfl_xor_sync(0xffffffffu, rm, 1));
                rm = fmaxf(rm, __shfl_xor_sync(0xffffffffu, rm, 2));
                float mn = fmaxf(m_[fm][hh], rm);
                float sum = 0.f;
                #pragma unroll
                for (int fn = 0; fn < 8; fn++){
                    s[fm][fn][hh*2]   = __expf(s[fm][fn][hh*2]   - mn);
                    s[fm][fn][hh*2+1] = __expf(s[fm][fn][hh*2+1] - mn);
                    sum += s[fm][fn][hh*2] + s[fm][fn][hh*2+1];
                }
                sum += __shfl_xor_sync(0xffffffffu, sum, 1);
                sum += __shfl_xor_sync(0xffffffffu, sum, 2);
                float alpha = __expf(m_[fm][hh] - mn);
                l_[fm][hh] = l_[fm][hh]*alpha + sum;
                m_[fm][hh] = mn;
                #pragma unroll
                for (int fn = 0; fn < 8; fn++){
                    o[fm][fn][hh*2]   *= alpha;
                    o[fm][fn][hh*2+1] *= alpha;
                }
            }

        // PV: P fragments built directly from S fragments (bit-identical to smem path)
        #pragma unroll
        for (int ks = 0; ks < 4; ks++){
            int kw = ks*8 + cb;
            unsigned a[2][4];
            #pragma unroll
            for (int fm = 0; fm < 2; fm++){
                a[fm][0] = pk(s[fm][2*ks][0],   s[fm][2*ks][1]);
                a[fm][1] = pk(s[fm][2*ks][2],   s[fm][2*ks][3]);
                a[fm][2] = pk(s[fm][2*ks+1][0], s[fm][2*ks+1][1]);
                a[fm][3] = pk(s[fm][2*ks+1][2], s[fm][2*ks+1][3]);
            }
            #pragma unroll
            for (int fn = 0; fn < 8; fn++){
                int n = fn*8 + rr;
                unsigned bb[2];
                bb[0] = Vc[n*36 + kw];
                bb[1] = Vc[n*36 + kw + 4];
                mma16(o[0][fn], a[0], bb);
                mma16(o[1][fn], a[1], bb);
            }
        }

        if (t + 1 < 32){
            int nxt = (cur^1)*2304;
            #pragma unroll
            for (int l=0;l<2;l++){
                *(uint4*)&sm[nxt + kp_[l]*36 + cq_[l]*4] = kst[l];
                *(uint4*)&sm[4608 + nxt + kp_[l]*36 + cq_[l]*4] = vst[l];
            }
            __syncthreads();
        }
    }

    unsigned* Hw = (unsigned*)H;
    #pragma unroll
    for (int fm = 0; fm < 2; fm++)
        #pragma unroll
        for (int hh = 0; hh < 2; hh++){
            float inv = 1.f / l_[fm][hh];
            int sg = qb*256 + w*32 + fm*16 + rr + 8*hh;
            size_t base = ((size_t)b*S_LEN + sg)*512 + hd*32;
            #pragma unroll
            for (int fn = 0; fn < 8; fn++)
                Hw[base + fn*4 + cb] = pk(o[fm][fn][hh*2]*inv, o[fm][fn][hh*2+1]*inv);
        }
}

extern "C" void kernel_launch(void* const* d_in, const int* in_sizes, int n_in,
                              void* d_out, int out_size)
{
    const float* X  = (const float*)d_in[0];
    const float* Wq = (const float*)d_in[1];
    const float* bq = (const float*)d_in[2];
    const float* Wk = (const float*)d_in[3];
    const float* bk = (const float*)d_in[4];
    const float* Wv = (const float*)d_in[5];
    const float* bv = (const float*)d_in[6];
    const float* Wo = (const float*)d_in[7];
    const float* bo = (const float*)d_in[8];
    float* out = (float*)d_out;

    __half *gq, *gk, *gvt, *gh, *gx, *gw;
    cudaGetSymbolAddress((void**)&gq, g_Qh);
    cudaGetSymbolAddress((void**)&gk, g_Kh);
    cudaGetSymbolAddress((void**)&gvt, g_VTh);
    cudaGetSymbolAddress((void**)&gh, g_Hh);
    cudaGetSymbolAddress((void**)&gx, g_Xh);
    cudaGetSymbolAddress((void**)&gw, g_Wh);

    const int attn_smem = 4*2304*4;   // 36864 B
    cudaFuncSetAttribute(attn_h, cudaFuncAttributeMaxDynamicSharedMemorySize, attn_smem);

    rope_table_kernel<<<(S_LEN*512 + 255)/256, 256>>>();

    const int X8 = M_TOT*D_DIM/8, W8 = D_DIM*D_DIM/8;
    conv_f16<<<(X8 + 255)/256, 256>>>(X, gx, X8);
    conv_f16<<<(W8 + 255)/256, 256>>>(Wq, gw + 0*D_DIM*D_DIM, W8);
    conv_f16<<<(W8 + 255)/256, 256>>>(Wk, gw + 1*D_DIM*D_DIM, W8);
    conv_f16<<<(W8 + 255)/256, 256>>>(Wv, gw + 2*D_DIM*D_DIM, W8);
    conv_f16<<<(W8 + 255)/256, 256>>>(Wo, gw + 3*D_DIM*D_DIM, W8);

    dim3 ggrid(D_DIM/128, M_TOT/128);   // (8, 64)
    gemm_h<2><<<ggrid, 128>>>(gx, gw + 0*D_DIM*D_DIM, bq, gq);
    gemm_h<2><<<ggrid, 128>>>(gx, gw + 1*D_DIM*D_DIM, bk, gk);
    gemm_h<3><<<ggrid, 128>>>(gx, gw + 2*D_DIM*D_DIM, bv, gvt);

    attn_h<<<dim3(S_LEN/256, NH, BATCH), 256, attn_smem>>>(gq, gk, gvt, gh);

    gemm_h<0><<<ggrid, 128>>>(gh, gw + 3*D_DIM*D_DIM, bo, out);
}

// round 11
// speedup vs baseline: 2.0047x; 1.0006x over previous
#include <cuda_runtime.h>
#include <cuda_fp16.h>
#include <math.h>
#include <stdint.h>

#define BATCH 4
#define S_LEN 2048
#define D_DIM 1024
#define NH    16
#define DH    64
#define M_TOT (BATCH*S_LEN)

__device__ __half g_Qh[BATCH*NH*S_LEN*DH];
__device__ __half g_Kh[BATCH*NH*S_LEN*DH];
__device__ __half g_VTh[BATCH*NH*DH*S_LEN];   // [b,h][dh][S]
__device__ __half g_Hh[M_TOT*D_DIM];
__device__ __half g_Xh[M_TOT*D_DIM];
__device__ __half g_Wh[4*D_DIM*D_DIM];
__device__ float2 g_tab[S_LEN*(D_DIM/2)];

__device__ __forceinline__ unsigned pk(float a, float b){
    __half2 h = __floats2half2_rn(a, b); return *(unsigned*)&h;
}
__device__ __forceinline__ void mma16(float* c, const unsigned* a, const unsigned* b){
    asm volatile("mma.sync.aligned.m16n8k16.row.col.f32.f16.f16.f32 "
        "{%0,%1,%2,%3}, {%4,%5,%6,%7}, {%8,%9}, {%0,%1,%2,%3};"
        : "+f"(c[0]), "+f"(c[1]), "+f"(c[2]), "+f"(c[3])
        : "r"(a[0]), "r"(a[1]), "r"(a[2]), "r"(a[3]), "r"(b[0]), "r"(b[1]));
}

__global__ void rope_table_kernel(){
    int idx = blockIdx.x*blockDim.x + threadIdx.x;
    if (idx >= S_LEN*512) return;
    int s = idx >> 9, p = idx & 511;
    double inv = exp(-((double)(2*p)/(double)D_DIM)*log(10000.0));
    float sn, cs; sincosf((float)s*(float)inv, &sn, &cs);
    g_tab[idx] = make_float2(cs, sn);
}

__global__ void conv_f16(const float* __restrict__ src, __half* __restrict__ dst, int n8){
    int i = blockIdx.x*blockDim.x + threadIdx.x;
    if (i >= n8) return;
    const float4* s = (const float4*)src + (size_t)i*2;
    float4 v0 = s[0], v1 = s[1];
    uint4 o;
    o.x = pk(v0.x, v0.y); o.y = pk(v0.z, v0.w);
    o.z = pk(v1.x, v1.y); o.w = pk(v1.z, v1.w);
    ((uint4*)dst)[i] = o;
}

// ============ fp16 GEMM: out = A[M,1024] @ W[N,1024]^T + bias ============
// 4 warps, warp 64x64, CTA 128x128, chunk k16 = 8 half2-words, double-buffered.
// MODE 0: fp32 [M,N]+bias; MODE 2: RoPE+half scatter [B,H,S,dh]; MODE 3: half scatter transposed [B,H,dh,S]
template<int MODE>
__global__ __launch_bounds__(128,2) void gemm_h(
    const __half* __restrict__ A, const __half* __restrict__ W,
    const float* __restrict__ bias, void* __restrict__ outv)
{
    __shared__ unsigned As[2][8*136], Bs[2][8*136];
    int tid = threadIdx.x, lane = tid & 31, w = tid >> 5;
    int rr = lane >> 2, cb = lane & 3;
    int wm = (w >> 1)*64, wn = (w & 1)*64;
    int m0 = blockIdx.y*128, n0 = blockIdx.x*128;

    float acc[4][8][4];
    #pragma unroll
    for (int i=0;i<4;i++)
        #pragma unroll
        for (int j=0;j<8;j++)
            #pragma unroll
            for (int e=0;e<4;e++) acc[i][j][e] = 0.f;

    const uint4* Ar[2]; const uint4* Wr[2];
    int mm[2], kk[2];
    #pragma unroll
    for (int l=0;l<2;l++){
        int slot = tid + l*128;
        mm[l] = slot >> 1; kk[l] = slot & 1;
        Ar[l] = (const uint4*)A + (size_t)(m0+mm[l])*128;
        Wr[l] = (const uint4*)W + (size_t)(n0+mm[l])*128;
    }

    uint4 av[2], bv[2];
    #pragma unroll
    for (int l=0;l<2;l++){ av[l] = Ar[l][kk[l]]; bv[l] = Wr[l][kk[l]]; }
    #pragma unroll
    for (int l=0;l<2;l++){
        const unsigned* a4 = (const unsigned*)&av[l];
        const unsigned* b4 = (const unsigned*)&bv[l];
        #pragma unroll
        for (int j=0;j<4;j++){
            As[0][(kk[l]*4+j)*136 + ((mm[l] + 8*kk[l]) & 127)] = a4[j];
            Bs[0][(kk[l]*4+j)*136 + ((mm[l] + 8*kk[l]) & 127)] = b4[j];
        }
    }
    __syncthreads();

    for (int it = 0; it < 64; it++){
        int cur = it & 1;
        if (it + 1 < 64){
            #pragma unroll
            for (int l=0;l<2;l++){
                av[l] = Ar[l][(it+1)*2 + kk[l]];
                bv[l] = Wr[l][(it+1)*2 + kk[l]];
            }
        }
        unsigned a[4][4], b[8][2];
        #pragma unroll
        for (int fm = 0; fm < 4; fm++){
            int r = wm + rr + fm*16;
            a[fm][0] = As[cur][cb*136 + (r & 127)];
            a[fm][1] = As[cur][cb*136 + ((r+8) & 127)];
            a[fm][2] = As[cur][(cb+4)*136 + ((r+8) & 127)];
            a[fm][3] = As[cur][(cb+4)*136 + ((r+16) & 127)];
        }
        #pragma unroll
        for (int fn = 0; fn < 8; fn++){
            int n = wn + rr + fn*8;
            b[fn][0] = Bs[cur][cb*136 + (n & 127)];
            b[fn][1] = Bs[cur][(cb+4)*136 + ((n+8) & 127)];
        }
        #pragma unroll
        for (int fm = 0; fm < 4; fm++)
            #pragma unroll
            for (int fn = 0; fn < 8; fn++)
                mma16(acc[fm][fn], a[fm], b[fn]);
        if (it + 1 < 64){
            int nxt = cur ^ 1;
            #pragma unroll
            for (int l=0;l<2;l++){
                const unsigned* a4 = (const unsigned*)&av[l];
                const unsigned* b4 = (const unsigned*)&bv[l];
                #pragma unroll
                for (int j=0;j<4;j++){
                    As[nxt][(kk[l]*4+j)*136 + ((mm[l] + 8*kk[l]) & 127)] = a4[j];
                    Bs[nxt][(kk[l]*4+j)*136 + ((mm[l] + 8*kk[l]) & 127)] = b4[j];
                }
            }
            __syncthreads();
        }
    }

    #pragma unroll
    for (int fn = 0; fn < 8; fn++){
        int colg = n0 + wn + fn*8 + cb*2;
        float b0v = bias[colg], b1v = bias[colg+1];
        #pragma unroll
        for (int fm = 0; fm < 4; fm++){
            #pragma unroll
            for (int half = 0; half < 2; half++){
                int mr = m0 + wm + fm*16 + rr + half*8;
                float v0 = acc[fm][fn][half*2+0] + b0v;
                float v1 = acc[fm][fn][half*2+1] + b1v;
                int srow = mr & (S_LEN-1);
                int bb = mr >> 11, hh = colg >> 6, dd = colg & 63;
                if (MODE == 2){
                    float2 cs = g_tab[srow*512 + (colg >> 1)];
                    float e = v0*cs.x - v1*cs.y;
                    float d = v0*cs.y + v1*cs.x;
                    v0 = e; v1 = d;
                }
                if (MODE == 0){
                    *(float2*)((float*)outv + (size_t)mr*D_DIM + colg) = make_float2(v0, v1);
                } else if (MODE == 2){
                    ((unsigned*)outv)[((size_t)(bb*NH+hh)*S_LEN + srow)*32 + (dd>>1)] = pk(v0, v1);
                } else {  // MODE 3: V transposed [b,h][dh][S]
                    __half* ov = (__half*)outv + ((size_t)(bb*NH+hh)*DH + dd)*S_LEN + srow;
                    ov[0] = __float2half(v0);
                    ov[S_LEN] = __float2half(v1);
                }
            }
        }
    }
}

// ============ fp16 flash attention: 8 warps x 32q x 64k, register-resident P ============
// K smem: Ks[kpos][kw] stride 36; VT smem: Vs[dh][kw] stride 36. One barrier per tile.
__global__ __launch_bounds__(256,1) void attn_h(
    const __half* __restrict__ Q, const __half* __restrict__ K,
    const __half* __restrict__ VT, __half* __restrict__ H)
{
    extern __shared__ unsigned sm[];
    // layout (words): K: [0, 2*2304), V: [4608, +2*2304)
    int tid = threadIdx.x, lane = tid & 31, w = tid >> 5;
    int rr = lane >> 2, cb = lane & 3;
    int qb = blockIdx.x, hd = blockIdx.y, b = blockIdx.z;
    int bh = b*NH + hd;

    const unsigned* Qw = (const unsigned*)(Q + ((size_t)bh*S_LEN + qb*256 + w*32)*DH);
    const uint4* Kg = (const uint4*)(K + (size_t)bh*S_LEN*DH);
    const uint4* Vg = (const uint4*)(VT + (size_t)bh*DH*S_LEN);

    const unsigned sc = 0x30003000u;  // half2(0.125, 0.125)
    unsigned q[2][4][4];
    #pragma unroll
    for (int fm = 0; fm < 2; fm++){
        int r0 = fm*16 + rr;
        #pragma unroll
        for (int ks = 0; ks < 4; ks++){
            int kw = ks*8 + cb;
            unsigned u0 = Qw[r0*32 + kw],     u1 = Qw[(r0+8)*32 + kw];
            unsigned u2 = Qw[r0*32 + kw + 4], u3 = Qw[(r0+8)*32 + kw + 4];
            __half2 s2 = *(__half2*)&sc;
            __half2 h0 = __hmul2(*(__half2*)&u0, s2), h1 = __hmul2(*(__half2*)&u1, s2);
            __half2 h2 = __hmul2(*(__half2*)&u2, s2), h3 = __hmul2(*(__half2*)&u3, s2);
            q[fm][ks][0] = *(unsigned*)&h0; q[fm][ks][1] = *(unsigned*)&h1;
            q[fm][ks][2] = *(unsigned*)&h2; q[fm][ks][3] = *(unsigned*)&h3;
        }
    }

    float m_[2][2], l_[2][2], o[2][8][4];
    #pragma unroll
    for (int fm=0;fm<2;fm++)
        #pragma unroll
        for (int hh=0;hh<2;hh++){ m_[fm][hh] = -1e30f; l_[fm][hh] = 0.f; }
    #pragma unroll
    for (int fm=0;fm<2;fm++)
        #pragma unroll
        for (int fn=0;fn<8;fn++)
            #pragma unroll
            for (int e=0;e<4;e++) o[fm][fn][e] = 0.f;

    uint4 kst[2], vst[2];
    int kp_[2], cq_[2];
    #pragma unroll
    for (int l=0;l<2;l++){ int slot = tid + l*256; kp_[l] = slot>>3; cq_[l] = slot&7; }

    // prologue tile 0
    #pragma unroll
    for (int l=0;l<2;l++){
        kst[l] = Kg[(size_t)kp_[l]*8 + cq_[l]];
        vst[l] = Vg[(size_t)kp_[l]*256 + cq_[l]];
    }
    #pragma unroll
    for (int l=0;l<2;l++){
        *(uint4*)&sm[kp_[l]*36 + cq_[l]*4] = kst[l];
        *(uint4*)&sm[4608 + kp_[l]*36 + cq_[l]*4] = vst[l];
    }
    __syncthreads();

    for (int t = 0; t < 32; t++){
        int cur = t & 1;
        const unsigned* Kc = sm + cur*2304;
        const unsigned* Vc = sm + 4608 + cur*2304;
        if (t + 1 < 32){
            #pragma unroll
            for (int l=0;l<2;l++){
                kst[l] = Kg[(size_t)((t+1)*64 + kp_[l])*8 + cq_[l]];
                vst[l] = Vg[(size_t)kp_[l]*256 + (t+1)*8 + cq_[l]];
            }
        }

        float s[2][8][4];
        #pragma unroll
        for (int fm=0;fm<2;fm++)
            #pragma unroll
            for (int fn=0;fn<8;fn++)
                #pragma unroll
                for (int e=0;e<4;e++) s[fm][fn][e] = 0.f;

        #pragma unroll
        for (int ks = 0; ks < 4; ks++){
            int kw = ks*8 + cb;
            #pragma unroll
            for (int fn = 0; fn < 8; fn++){
                int n = fn*8 + rr;
                unsigned bb[2];
                bb[0] = Kc[n*36 + kw];
                bb[1] = Kc[n*36 + kw + 4];
                mma16(s[0][fn], q[0][ks], bb);
                mma16(s[1][fn], q[1][ks], bb);
            }
        }

        #pragma unroll
        for (int fm = 0; fm < 2; fm++)
            #pragma unroll
            for (int hh = 0; hh < 2; hh++){
                float rm = -1e30f;
                #pragma unroll
                for (int fn = 0; fn < 8; fn++)
                    rm = fmaxf(rm, fmaxf(s[fm][fn][hh*2], s[fm][fn][hh*2+1]));
                rm = fmaxf(rm, __shfl_xor_sync(0xffffffffu, rm, 1));
                rm = fmaxf(rm, __shfl_xor_sync(0xffffffffu, rm, 2));
                float mn = fmaxf(m_[fm][hh], rm);
                float sum = 0.f;
                #pragma unroll
                for (int fn = 0; fn < 8; fn++){
                    s[fm][fn][hh*2]   = __expf(s[fm][fn][hh*2]   - mn);
                    s[fm][fn][hh*2+1] = __expf(s[fm][fn][hh*2+1] - mn);
                    sum += s[fm][fn][hh*2] + s[fm][fn][hh*2+1];
                }
                sum += __shfl_xor_sync(0xffffffffu, sum, 1);
                sum += __shfl_xor_sync(0xffffffffu, sum, 2);
                float alpha = __expf(m_[fm][hh] - mn);
                l_[fm][hh] = l_[fm][hh]*alpha + sum;
                m_[fm][hh] = mn;
                #pragma unroll
                for (int fn = 0; fn < 8; fn++){
                    o[fm][fn][hh*2]   *= alpha;
                    o[fm][fn][hh*2+1] *= alpha;
                }
            }

        // PV: P fragments built directly from S fragments (bit-identical to smem path)
        #pragma unroll
        for (int ks = 0; ks < 4; ks++){
            int kw = ks*8 + cb;
            unsigned a[2][4];
            #pragma unroll
            for (int fm = 0; fm < 2; fm++){
                a[fm][0] = pk(s[fm][2*ks][0],   s[fm][2*ks][1]);
                a[fm][1] = pk(s[fm][2*ks][2],   s[fm][2*ks][3]);
                a[fm][2] = pk(s[fm][2*ks+1][0], s[fm][2*ks+1][1]);
                a[fm][3] = pk(s[fm][2*ks+1][2], s[fm][2*ks+1][3]);
            }
            #pragma unroll
            for (int fn = 0; fn < 8; fn++){
                int n = fn*8 + rr;
                unsigned bb[2];
                bb[0] = Vc[n*36 + kw];
                bb[1] = Vc[n*36 + kw + 4];
                mma16(o[0][fn], a[0], bb);
                mma16(o[1][fn], a[1], bb);
            }
        }

        if (t + 1 < 32){
            int nxt = (cur^1)*2304;
            #pragma unroll
            for (int l=0;l<2;l++){
                *(uint4*)&sm[nxt + kp_[l]*36 + cq_[l]*4] = kst[l];
                *(uint4*)&sm[4608 + nxt + kp_[l]*36 + cq_[l]*4] = vst[l];
            }
            __syncthreads();
        }
    }

    unsigned* Hw = (unsigned*)H;
    #pragma unroll
    for (int fm = 0; fm < 2; fm++)
        #pragma unroll
        for (int hh = 0; hh < 2; hh++){
            float inv = 1.f / l_[fm][hh];
            int sg = qb*256 + w*32 + fm*16 + rr + 8*hh;
            size_t base = ((size_t)b*S_LEN + sg)*512 + hd*32;
            #pragma unroll
            for (int fn = 0; fn < 8; fn++)
                Hw[base + fn*4 + cb] = pk(o[fm][fn][hh*2]*inv, o[fm][fn][hh*2+1]*inv);
        }
}

extern "C" void kernel_launch(void* const* d_in, const int* in_sizes, int n_in,
                              void* d_out, int out_size)
{
    const float* X  = (const float*)d_in[0];
    const float* Wq = (const float*)d_in[1];
    const float* bq = (const float*)d_in[2];
    const float* Wk = (const float*)d_in[3];
    const float* bk = (const float*)d_in[4];
    const float* Wv = (const float*)d_in[5];
    const float* bv = (const float*)d_in[6];
    const float* Wo = (const float*)d_in[7];
    const float* bo = (const float*)d_in[8];
    float* out = (float*)d_out;

    __half *gq, *gk, *gvt, *gh, *gx, *gw;
    cudaGetSymbolAddress((void**)&gq, g_Qh);
    cudaGetSymbolAddress((void**)&gk, g_Kh);
    cudaGetSymbolAddress((void**)&gvt, g_VTh);
    cudaGetSymbolAddress((void**)&gh, g_Hh);
    cudaGetSymbolAddress((void**)&gx, g_Xh);
    cudaGetSymbolAddress((void**)&gw, g_Wh);

    const int attn_smem = 4*2304*4;   // 36864 B
    cudaFuncSetAttribute(attn_h, cudaFuncAttributeMaxDynamicSharedMemorySize, attn_smem);

    rope_table_kernel<<<(S_LEN*512 + 255)/256, 256>>>();

    const int X8 = M_TOT*D_DIM/8, W8 = D_DIM*D_DIM/8;
    conv_f16<<<(X8 + 255)/256, 256>>>(X, gx, X8);
    conv_f16<<<(W8 + 255)/256, 256>>>(Wq, gw + 0*D_DIM*D_DIM, W8);
    conv_f16<<<(W8 + 255)/256, 256>>>(Wk, gw + 1*D_DIM*D_DIM, W8);
    conv_f16<<<(W8 + 255)/256, 256>>>(Wv, gw + 2*D_DIM*D_DIM, W8);
    conv_f16<<<(W8 + 255)/256, 256>>>(Wo, gw + 3*D_DIM*D_DIM, W8);

    dim3 ggrid(D_DIM/128, M_TOT/128);   // (8, 64)
    gemm_h<2><<<ggrid, 128>>>(gx, gw + 0*D_DIM*D_DIM, bq, gq);
    gemm_h<2><<<ggrid, 128>>>(gx, gw + 1*D_DIM*D_DIM, bk, gk);
    gemm_h<3><<<ggrid, 128>>>(gx, gw + 2*D_DIM*D_DIM, bv, gvt);

    attn_h<<<dim3(S_LEN/256, NH, BATCH), 256, attn_smem>>>(gq, gk, gvt, gh);

    gemm_h<0><<<ggrid, 128>>>(gh, gw + 3*D_DIM*D_DIM, bo, out);
}